// round 4
// baseline (speedup 1.0000x reference)
#include <cuda_runtime.h>
#include <cuda_bf16.h>
#include <math.h>

#define Nn 20000
#define Tt 256
#define Ee 320000
#define Gg 64
#define CT 8
#define CP 16
#define EMB 768
#define OUTC 4
#define FIN 512
#define BN_EPS 1e-5f

// ---------------- scratch (device globals, no allocation) ----------------
__device__ float g_h0[(size_t)Nn * FIN];      // conv output, 41 MB
__device__ float g_agg1[(size_t)Nn * FIN];    // 41 MB
__device__ float g_z[(size_t)Nn * EMB];       // 61 MB (reused z1/z2)
__device__ float g_h1[(size_t)Nn * EMB];      // 61 MB
__device__ float g_agg2[(size_t)Nn * EMB];    // 61 MB
__device__ float g_h2[(size_t)Nn * EMB];      // 61 MB
__device__ float g_sums[Gg * EMB];
__device__ float g_cnt[Gg];

// ---------------- fused temporal conv + BN + pool ----------------
// One block per node, 256 threads (one per time step).
__global__ void __launch_bounds__(256) conv_kernel(
    const float* __restrict__ x,
    const float* __restrict__ w0,
    const float* __restrict__ g0, const float* __restrict__ b0,
    const float* __restrict__ m0, const float* __restrict__ v0,
    const float* __restrict__ w1,
    const float* __restrict__ w2,
    const float* __restrict__ g2, const float* __restrict__ b2,
    const float* __restrict__ m2, const float* __restrict__ v2,
    float* __restrict__ hout)
{
    __shared__ float xs[256];
    __shared__ float w0s[33 * 8];
    __shared__ float w1s[21 * 8];
    __shared__ float w2s[8 * 16];
    __shared__ float sc0[8], sh0[8], sc2[16], sh2[16];
    __shared__ float s1s[8][264];  // [channel][time] to keep stage-2 reads conflict free

    const int t = threadIdx.x;
    const int n = blockIdx.x;

    xs[t] = x[(size_t)n * Tt + t];
    // NOTE: 33*8 = 264 > 256 threads -> must stride (this was the round-3 bug)
    for (int i = t; i < 33 * 8; i += 256) w0s[i] = w0[i];
    if (t < 21 * 8) w1s[t] = w1[t];
    if (t < 8 * 16) w2s[t] = w2[t];
    if (t < 8)  { float s = g0[t] * rsqrtf(v0[t] + BN_EPS); sc0[t] = s; sh0[t] = b0[t] - m0[t] * s; }
    if (t < 16) { float s = g2[t] * rsqrtf(v2[t] + BN_EPS); sc2[t] = s; sh2[t] = b2[t] - m2[t] * s; }
    __syncthreads();

    // stage 1: conv0 (1 -> 8 channels, k=33, SAME) + bn0
    float acc[8];
#pragma unroll
    for (int c = 0; c < 8; c++) acc[c] = 0.f;
#pragma unroll
    for (int w = 0; w < 33; w++) {
        int tt = t + w - 16;
        float xv = (tt >= 0 && tt < 256) ? xs[tt] : 0.f;
#pragma unroll
        for (int c = 0; c < 8; c++) acc[c] += xv * w0s[w * 8 + c];
    }
#pragma unroll
    for (int c = 0; c < 8; c++) s1s[c][t] = acc[c] * sc0[c] + sh0[c];
    __syncthreads();

    // stage 2: depthwise conv (k=21, SAME) + relu
    float s2[8];
#pragma unroll
    for (int c = 0; c < 8; c++) {
        float a = 0.f;
#pragma unroll
        for (int w = 0; w < 21; w++) {
            int tt = t + w - 10;
            float xv = (tt >= 0 && tt < 256) ? s1s[c][tt] : 0.f;
            a += xv * w1s[w * 8 + c];
        }
        s2[c] = fmaxf(a, 0.f);
    }

    // stage 3: 1x1 conv (8 -> 16) + bn2 + relu, then mean-pool over 8 time steps
    const int lane = t & 31;
#pragma unroll
    for (int o = 0; o < 16; o++) {
        float a = 0.f;
#pragma unroll
        for (int c = 0; c < 8; c++) a += s2[c] * w2s[c * 16 + o];
        a = fmaxf(a * sc2[o] + sh2[o], 0.f);
        // sum over 8-lane group (time window of 8 is contiguous in lanes)
        a += __shfl_xor_sync(0xffffffffu, a, 1);
        a += __shfl_xor_sync(0xffffffffu, a, 2);
        a += __shfl_xor_sync(0xffffffffu, a, 4);
        if ((lane & 7) == 0)
            hout[(size_t)n * FIN + (t >> 3) * 16 + o] = a * 0.125f;
    }
}

// ---------------- utility: zero buffer (float4) ----------------
__global__ void zero_kernel(float4* __restrict__ p, int n4)
{
    int i = blockIdx.x * blockDim.x + threadIdx.x;
    int stride = gridDim.x * blockDim.x;
    float4 z = make_float4(0.f, 0.f, 0.f, 0.f);
    for (; i < n4; i += stride) p[i] = z;
}

// ---------------- edge aggregation: agg[dst] += h[src] ----------------
template <int F>
__global__ void __launch_bounds__(F / 4) edge_agg_kernel(
    const int* __restrict__ ei, const float* __restrict__ h, float* __restrict__ agg)
{
    const int e = blockIdx.x;
    const int src = ei[e];
    const int dst = ei[Ee + e];
    const int f = threadIdx.x;  // F/4 threads
    float4 v = *(const float4*)(h + (size_t)src * F + f * 4);
    float* a = agg + (size_t)dst * F + f * 4;
    atomicAdd(a + 0, v.x);
    atomicAdd(a + 1, v.y);
    atomicAdd(a + 2, v.z);
    atomicAdd(a + 3, v.w);
}

// ---------------- fp32 tiled GEMM: C = act((A [+A2]) @ B + bias) ----------------
// A: Nrows x K row-major, B: K x M row-major, C: Nrows x M. 64x64 tile, BK=16.
template <bool ADD>
__global__ void __launch_bounds__(256) gemm_kernel(
    const float* __restrict__ A, const float* __restrict__ A2,
    const float* __restrict__ B, const float* __restrict__ bias,
    float* __restrict__ C, int Nrows, int K, int M, int doRelu)
{
    __shared__ float As[16][64];
    __shared__ float Bs[16][64];

    const int tid = threadIdx.x;
    const int tx = tid & 15;
    const int ty = tid >> 4;
    const int rowBase = blockIdx.y * 64;
    const int colBase = blockIdx.x * 64;

    const int aRow = tid >> 2;        // 0..63
    const int aK = (tid & 3) * 4;     // 0,4,8,12
    const int bK = tid >> 4;          // 0..15
    const int bCol = (tid & 15) * 4;  // 0..60

    const bool aValid = (rowBase + aRow) < Nrows;
    const float* aPtr = A + (size_t)(rowBase + aRow) * K + aK;
    const float* a2Ptr = ADD ? (A2 + (size_t)(rowBase + aRow) * K + aK) : nullptr;
    const float* bPtr = B + (size_t)bK * M + colBase + bCol;

    float acc[4][4];
#pragma unroll
    for (int i = 0; i < 4; i++)
#pragma unroll
        for (int j = 0; j < 4; j++) acc[i][j] = 0.f;

    for (int k0 = 0; k0 < K; k0 += 16) {
        float4 av = make_float4(0.f, 0.f, 0.f, 0.f);
        if (aValid) {
            av = *(const float4*)(aPtr + k0);
            if (ADD) {
                float4 a2 = *(const float4*)(a2Ptr + k0);
                av.x += a2.x; av.y += a2.y; av.z += a2.z; av.w += a2.w;
            }
        }
        As[aK + 0][aRow] = av.x;
        As[aK + 1][aRow] = av.y;
        As[aK + 2][aRow] = av.z;
        As[aK + 3][aRow] = av.w;
        *(float4*)&Bs[bK][bCol] = *(const float4*)(bPtr + (size_t)k0 * M);
        __syncthreads();
#pragma unroll
        for (int kk = 0; kk < 16; kk++) {
            float4 a = *(float4*)&As[kk][ty * 4];
            float4 b = *(float4*)&Bs[kk][tx * 4];
            acc[0][0] += a.x * b.x; acc[0][1] += a.x * b.y; acc[0][2] += a.x * b.z; acc[0][3] += a.x * b.w;
            acc[1][0] += a.y * b.x; acc[1][1] += a.y * b.y; acc[1][2] += a.y * b.z; acc[1][3] += a.y * b.w;
            acc[2][0] += a.z * b.x; acc[2][1] += a.z * b.y; acc[2][2] += a.z * b.z; acc[2][3] += a.z * b.w;
            acc[3][0] += a.w * b.x; acc[3][1] += a.w * b.y; acc[3][2] += a.w * b.z; acc[3][3] += a.w * b.w;
        }
        __syncthreads();
    }

#pragma unroll
    for (int i = 0; i < 4; i++) {
        int r = rowBase + ty * 4 + i;
        if (r < Nrows) {
#pragma unroll
            for (int j = 0; j < 4; j++) {
                int c = colBase + tx * 4 + j;
                float v = acc[i][j] + bias[c];
                if (doRelu) v = fmaxf(v, 0.f);
                C[(size_t)r * M + c] = v;
            }
        }
    }
}

// ---------------- graph mean-pool: sums/counts ----------------
__global__ void __launch_bounds__(192) pool_kernel(
    const int* __restrict__ batch, const float* __restrict__ h,
    float* __restrict__ sums, float* __restrict__ cnt)
{
    const int n = blockIdx.x;
    const int b = batch[n];
    const int f = threadIdx.x;  // 192
    float4 v = *(const float4*)(h + (size_t)n * EMB + f * 4);
    float* s = sums + (size_t)b * EMB + f * 4;
    atomicAdd(s + 0, v.x);
    atomicAdd(s + 1, v.y);
    atomicAdd(s + 2, v.z);
    atomicAdd(s + 3, v.w);
    if (f == 0) atomicAdd(&cnt[b], 1.0f);
}

// ---------------- head: mean, dense, log_softmax ----------------
__global__ void __launch_bounds__(192) head_kernel(
    const float* __restrict__ sums, const float* __restrict__ cnt,
    const float* __restrict__ W, const float* __restrict__ bias,
    float* __restrict__ out)
{
    __shared__ float red[192][4];
    const int g = blockIdx.x;
    const int t = threadIdx.x;  // 192
    const float c = fmaxf(cnt[g], 1.f);
    float4 p = *(const float4*)(sums + (size_t)g * EMB + t * 4);
    const float inv = 1.f / c;
    p.x *= inv; p.y *= inv; p.z *= inv; p.w *= inv;
    const int f = t * 4;
#pragma unroll
    for (int o = 0; o < 4; o++) {
        red[t][o] = p.x * W[(f + 0) * 4 + o] + p.y * W[(f + 1) * 4 + o] +
                    p.z * W[(f + 2) * 4 + o] + p.w * W[(f + 3) * 4 + o];
    }
    __syncthreads();
    if (t == 0) {
        float l[4];
#pragma unroll
        for (int o = 0; o < 4; o++) {
            float s = bias[o];
            for (int i = 0; i < 192; i++) s += red[i][o];
            l[o] = s;
        }
        float m = fmaxf(fmaxf(l[0], l[1]), fmaxf(l[2], l[3]));
        float se = expf(l[0] - m) + expf(l[1] - m) + expf(l[2] - m) + expf(l[3] - m);
        float lse = m + logf(se);
#pragma unroll
        for (int o = 0; o < 4; o++) out[g * 4 + o] = l[o] - lse;
    }
}

// ---------------- launch ----------------
extern "C" void kernel_launch(void* const* d_in, const int* in_sizes, int n_in,
                              void* d_out, int out_size)
{
    const float* x       = (const float*)d_in[0];
    const int*   ei      = (const int*)d_in[1];
    const int*   batch   = (const int*)d_in[2];
    const float* conv0_w = (const float*)d_in[3];
    const float* bn0_g   = (const float*)d_in[4];
    const float* bn0_b   = (const float*)d_in[5];
    const float* bn0_m   = (const float*)d_in[6];
    const float* bn0_v   = (const float*)d_in[7];
    const float* conv1_w = (const float*)d_in[8];
    const float* conv2_w = (const float*)d_in[9];
    const float* bn2_g   = (const float*)d_in[10];
    const float* bn2_b   = (const float*)d_in[11];
    const float* bn2_m   = (const float*)d_in[12];
    const float* bn2_v   = (const float*)d_in[13];
    const float* g1w1    = (const float*)d_in[14];
    const float* g1b1    = (const float*)d_in[15];
    const float* g1w2    = (const float*)d_in[16];
    const float* g1b2    = (const float*)d_in[17];
    const float* g2w1    = (const float*)d_in[18];
    const float* g2b1    = (const float*)d_in[19];
    const float* g2w2    = (const float*)d_in[20];
    const float* g2b2    = (const float*)d_in[21];
    const float* dW      = (const float*)d_in[22];
    const float* dB      = (const float*)d_in[23];
    float* out = (float*)d_out;

    float *p_h0, *p_agg1, *p_z, *p_h1, *p_agg2, *p_h2, *p_sums, *p_cnt;
    cudaGetSymbolAddress((void**)&p_h0,   g_h0);
    cudaGetSymbolAddress((void**)&p_agg1, g_agg1);
    cudaGetSymbolAddress((void**)&p_z,    g_z);
    cudaGetSymbolAddress((void**)&p_h1,   g_h1);
    cudaGetSymbolAddress((void**)&p_agg2, g_agg2);
    cudaGetSymbolAddress((void**)&p_h2,   g_h2);
    cudaGetSymbolAddress((void**)&p_sums, g_sums);
    cudaGetSymbolAddress((void**)&p_cnt,  g_cnt);

    // 1) temporal conv stack -> h0 (N x 512)
    conv_kernel<<<Nn, 256>>>(x, conv0_w, bn0_g, bn0_b, bn0_m, bn0_v,
                             conv1_w, conv2_w, bn2_g, bn2_b, bn2_m, bn2_v, p_h0);

    // 2) GIN1 aggregation
    {
        int n4 = Nn * FIN / 4;
        zero_kernel<<<(n4 + 255) / 256, 256>>>((float4*)p_agg1, n4);
        edge_agg_kernel<FIN><<<Ee, FIN / 4>>>(ei, p_h0, p_agg1);
    }
    // 3) z1 = relu((h0+agg1)@W1 + b1), h1 = relu(z1@W2 + b2)
    {
        dim3 grid1(EMB / 64, (Nn + 63) / 64);
        gemm_kernel<true><<<grid1, 256>>>(p_h0, p_agg1, g1w1, g1b1, p_z, Nn, FIN, EMB, 1);
        gemm_kernel<false><<<grid1, 256>>>(p_z, nullptr, g1w2, g1b2, p_h1, Nn, EMB, EMB, 1);
    }
    // 4) GIN2 aggregation
    {
        int n4 = Nn * EMB / 4;
        zero_kernel<<<(n4 + 255) / 256, 256>>>((float4*)p_agg2, n4);
        edge_agg_kernel<EMB><<<Ee, EMB / 4>>>(ei, p_h1, p_agg2);
    }
    // 5) z2 = relu((h1+agg2)@W3 + b3), h2 = relu(z2@W4 + b4)
    {
        dim3 grid1(EMB / 64, (Nn + 63) / 64);
        gemm_kernel<true><<<grid1, 256>>>(p_h1, p_agg2, g2w1, g2b1, p_z, Nn, EMB, EMB, 1);
        gemm_kernel<false><<<grid1, 256>>>(p_z, nullptr, g2w2, g2b2, p_h2, Nn, EMB, EMB, 1);
    }
    // 6) graph mean pool + dense + log_softmax
    {
        int n4s = Gg * EMB / 4;
        zero_kernel<<<(n4s + 255) / 256, 256>>>((float4*)p_sums, n4s);
        zero_kernel<<<1, 256>>>((float4*)p_cnt, Gg / 4);
        pool_kernel<<<Nn, EMB / 4>>>(batch, p_h2, p_sums, p_cnt);
        head_kernel<<<Gg, EMB / 4>>>(p_sums, p_cnt, dW, dB, out);
    }
}

// round 5
// speedup vs baseline: 1.1556x; 1.1556x over previous
#include <cuda_runtime.h>
#include <cuda_bf16.h>
#include <math.h>
#include <stdint.h>

#define Nn 20000
#define Tt 256
#define Ee 320000
#define Gg 64
#define CT 8
#define CP 16
#define EMB 768
#define OUTC 4
#define FIN 512
#define BN_EPS 1e-5f

// ---------------- scratch (device globals, no allocation) ----------------
__device__ float g_h0[(size_t)Nn * FIN];      // conv output, 41 MB
__device__ float g_agg1[(size_t)Nn * FIN];    // 41 MB
__device__ float g_z[(size_t)Nn * EMB];       // 61 MB (reused z1/z2)
__device__ float g_h1[(size_t)Nn * EMB];      // 61 MB
__device__ float g_agg2[(size_t)Nn * EMB];    // 61 MB
__device__ float g_h2[(size_t)Nn * EMB];      // 61 MB
__device__ float g_sums[Gg * EMB];
__device__ float g_cnt[Gg];

// ---------------- fused temporal conv + BN + pool ----------------
__global__ void __launch_bounds__(256) conv_kernel(
    const float* __restrict__ x,
    const float* __restrict__ w0,
    const float* __restrict__ g0, const float* __restrict__ b0,
    const float* __restrict__ m0, const float* __restrict__ v0,
    const float* __restrict__ w1,
    const float* __restrict__ w2,
    const float* __restrict__ g2, const float* __restrict__ b2,
    const float* __restrict__ m2, const float* __restrict__ v2,
    float* __restrict__ hout)
{
    __shared__ float xs[256];
    __shared__ float w0s[33 * 8];
    __shared__ float w1s[21 * 8];
    __shared__ float w2s[8 * 16];
    __shared__ float sc0[8], sh0[8], sc2[16], sh2[16];
    __shared__ float s1s[8][264];

    const int t = threadIdx.x;
    const int n = blockIdx.x;

    xs[t] = x[(size_t)n * Tt + t];
    for (int i = t; i < 33 * 8; i += 256) w0s[i] = w0[i];
    if (t < 21 * 8) w1s[t] = w1[t];
    if (t < 8 * 16) w2s[t] = w2[t];
    if (t < 8)  { float s = g0[t] * rsqrtf(v0[t] + BN_EPS); sc0[t] = s; sh0[t] = b0[t] - m0[t] * s; }
    if (t < 16) { float s = g2[t] * rsqrtf(v2[t] + BN_EPS); sc2[t] = s; sh2[t] = b2[t] - m2[t] * s; }
    __syncthreads();

    float acc[8];
#pragma unroll
    for (int c = 0; c < 8; c++) acc[c] = 0.f;
#pragma unroll
    for (int w = 0; w < 33; w++) {
        int tt = t + w - 16;
        float xv = (tt >= 0 && tt < 256) ? xs[tt] : 0.f;
#pragma unroll
        for (int c = 0; c < 8; c++) acc[c] += xv * w0s[w * 8 + c];
    }
#pragma unroll
    for (int c = 0; c < 8; c++) s1s[c][t] = acc[c] * sc0[c] + sh0[c];
    __syncthreads();

    float s2[8];
#pragma unroll
    for (int c = 0; c < 8; c++) {
        float a = 0.f;
#pragma unroll
        for (int w = 0; w < 21; w++) {
            int tt = t + w - 10;
            float xv = (tt >= 0 && tt < 256) ? s1s[c][tt] : 0.f;
            a += xv * w1s[w * 8 + c];
        }
        s2[c] = fmaxf(a, 0.f);
    }

    const int lane = t & 31;
#pragma unroll
    for (int o = 0; o < 16; o++) {
        float a = 0.f;
#pragma unroll
        for (int c = 0; c < 8; c++) a += s2[c] * w2s[c * 16 + o];
        a = fmaxf(a * sc2[o] + sh2[o], 0.f);
        a += __shfl_xor_sync(0xffffffffu, a, 1);
        a += __shfl_xor_sync(0xffffffffu, a, 2);
        a += __shfl_xor_sync(0xffffffffu, a, 4);
        if ((lane & 7) == 0)
            hout[(size_t)n * FIN + (t >> 3) * 16 + o] = a * 0.125f;
    }
}

// ---------------- utility: zero buffer (float4) ----------------
__global__ void zero_kernel(float4* __restrict__ p, int n4)
{
    int i = blockIdx.x * blockDim.x + threadIdx.x;
    int stride = gridDim.x * blockDim.x;
    float4 z = make_float4(0.f, 0.f, 0.f, 0.f);
    for (; i < n4; i += stride) p[i] = z;
}

// ---------------- edge aggregation: agg[dst] += h[src] ----------------
template <int F>
__global__ void __launch_bounds__(F / 4) edge_agg_kernel(
    const int* __restrict__ ei, const float* __restrict__ h, float* __restrict__ agg)
{
    const int e = blockIdx.x;
    const int src = ei[e];
    const int dst = ei[Ee + e];
    const int f = threadIdx.x;
    float4 v = *(const float4*)(h + (size_t)src * F + f * 4);
    float* a = agg + (size_t)dst * F + f * 4;
    atomicAdd(a + 0, v.x);
    atomicAdd(a + 1, v.y);
    atomicAdd(a + 2, v.z);
    atomicAdd(a + 3, v.w);
}

// ---------------- tf32 tensor-core GEMM (3xTF32 split, ~fp32 accuracy) ----
// C = act((A [+A2]) @ B + bias); A: Nrows x K (row-major), B: K x M (row-major).
// Block tile 128x128, BK=16, 256 threads, 8 warps as 4(m) x 2(n), warp tile 32x64.
#define BM 128
#define BN 128
#define BK 16
#define AS_STRIDE 20   // BK + 4: conflict-free frag loads, 16B-aligned rows
#define BS_STRIDE 136  // BN + 8: conflict-free frag loads, 16B-aligned rows

__device__ __forceinline__ uint32_t f2tf32(float x) {
    uint32_t r;
    asm("cvt.rna.tf32.f32 %0, %1;" : "=r"(r) : "f"(x));
    return r;
}

__device__ __forceinline__ void mma_tf32(
    float& d0, float& d1, float& d2, float& d3,
    uint32_t a0, uint32_t a1, uint32_t a2, uint32_t a3,
    uint32_t b0, uint32_t b1)
{
    asm volatile(
        "mma.sync.aligned.m16n8k8.row.col.f32.tf32.tf32.f32 "
        "{%0,%1,%2,%3}, {%4,%5,%6,%7}, {%8,%9}, {%0,%1,%2,%3};"
        : "+f"(d0), "+f"(d1), "+f"(d2), "+f"(d3)
        : "r"(a0), "r"(a1), "r"(a2), "r"(a3), "r"(b0), "r"(b1));
}

template <bool ADD>
__global__ void __launch_bounds__(256) gemm_tc_kernel(
    const float* __restrict__ A, const float* __restrict__ A2,
    const float* __restrict__ B, const float* __restrict__ bias,
    float* __restrict__ C, int Nrows, int K, int M, int doRelu)
{
    __shared__ uint32_t As_hi[BM][AS_STRIDE];
    __shared__ uint32_t As_lo[BM][AS_STRIDE];
    __shared__ uint32_t Bs_hi[BK][BS_STRIDE];
    __shared__ uint32_t Bs_lo[BK][BS_STRIDE];

    const int tid = threadIdx.x;
    const int lane = tid & 31;
    const int warp = tid >> 5;
    const int warp_m = warp & 3;   // 0..3 -> rows warp_m*32
    const int warp_n = warp >> 2;  // 0..1 -> cols warp_n*64
    const int rowBase = blockIdx.y * BM;
    const int colBase = blockIdx.x * BN;

    // global load mapping
    // A: 128 rows x 4 float4 (16 floats) = 512 float4; thread does id, id+256
    const int aRow0 = tid >> 2;          // 0..63
    const int aC4 = tid & 3;             // 0..3
    // B: 16 k x 32 float4 = 512 float4
    const int bK = tid >> 4;             // 0..15
    const int bC4a = tid & 15;           // 0..15
    // second: bC4a + 16

    float acc[2][8][4];
#pragma unroll
    for (int i = 0; i < 2; i++)
#pragma unroll
        for (int j = 0; j < 8; j++)
#pragma unroll
            for (int r = 0; r < 4; r++) acc[i][j][r] = 0.f;

    // prefetch first chunk
    float4 aReg[2], bReg[2];
    {
        const int k0 = 0;
#pragma unroll
        for (int h = 0; h < 2; h++) {
            int r = rowBase + aRow0 + h * 64;
            if (r < Nrows) {
                aReg[h] = *(const float4*)(A + (size_t)r * K + k0 + aC4 * 4);
                if (ADD) {
                    float4 a2 = *(const float4*)(A2 + (size_t)r * K + k0 + aC4 * 4);
                    aReg[h].x += a2.x; aReg[h].y += a2.y; aReg[h].z += a2.z; aReg[h].w += a2.w;
                }
            } else {
                aReg[h] = make_float4(0.f, 0.f, 0.f, 0.f);
            }
        }
#pragma unroll
        for (int h = 0; h < 2; h++) {
            bReg[h] = *(const float4*)(B + (size_t)(k0 + bK) * M + colBase + (bC4a + h * 16) * 4);
        }
    }

    for (int k0 = 0; k0 < K; k0 += BK) {
        // store staged regs to smem (hi/lo split)
#pragma unroll
        for (int h = 0; h < 2; h++) {
            int r = aRow0 + h * 64;
            float v[4] = {aReg[h].x, aReg[h].y, aReg[h].z, aReg[h].w};
            uint32_t hi[4], lo[4];
#pragma unroll
            for (int q = 0; q < 4; q++) {
                hi[q] = f2tf32(v[q]);
                lo[q] = f2tf32(v[q] - __uint_as_float(hi[q]));
            }
            *(uint4*)&As_hi[r][aC4 * 4] = make_uint4(hi[0], hi[1], hi[2], hi[3]);
            *(uint4*)&As_lo[r][aC4 * 4] = make_uint4(lo[0], lo[1], lo[2], lo[3]);
        }
#pragma unroll
        for (int h = 0; h < 2; h++) {
            float v[4] = {bReg[h].x, bReg[h].y, bReg[h].z, bReg[h].w};
            uint32_t hi[4], lo[4];
#pragma unroll
            for (int q = 0; q < 4; q++) {
                hi[q] = f2tf32(v[q]);
                lo[q] = f2tf32(v[q] - __uint_as_float(hi[q]));
            }
            *(uint4*)&Bs_hi[bK][(bC4a + h * 16) * 4] = make_uint4(hi[0], hi[1], hi[2], hi[3]);
            *(uint4*)&Bs_lo[bK][(bC4a + h * 16) * 4] = make_uint4(lo[0], lo[1], lo[2], lo[3]);
        }
        __syncthreads();

        // prefetch next chunk
        if (k0 + BK < K) {
            const int kn = k0 + BK;
#pragma unroll
            for (int h = 0; h < 2; h++) {
                int r = rowBase + aRow0 + h * 64;
                if (r < Nrows) {
                    aReg[h] = *(const float4*)(A + (size_t)r * K + kn + aC4 * 4);
                    if (ADD) {
                        float4 a2 = *(const float4*)(A2 + (size_t)r * K + kn + aC4 * 4);
                        aReg[h].x += a2.x; aReg[h].y += a2.y; aReg[h].z += a2.z; aReg[h].w += a2.w;
                    }
                } else {
                    aReg[h] = make_float4(0.f, 0.f, 0.f, 0.f);
                }
            }
#pragma unroll
            for (int h = 0; h < 2; h++) {
                bReg[h] = *(const float4*)(B + (size_t)(kn + bK) * M + colBase + (bC4a + h * 16) * 4);
            }
        }

        // compute: two k8 steps
#pragma unroll
        for (int kk = 0; kk < BK; kk += 8) {
            // A fragments for the warp's 2 m-tiles
            uint32_t ahi[2][4], alo[2][4];
#pragma unroll
            for (int i = 0; i < 2; i++) {
                int mr = warp_m * 32 + i * 16 + (lane >> 2);
                int kc = kk + (lane & 3);
                ahi[i][0] = As_hi[mr][kc];
                ahi[i][1] = As_hi[mr + 8][kc];
                ahi[i][2] = As_hi[mr][kc + 4];
                ahi[i][3] = As_hi[mr + 8][kc + 4];
                alo[i][0] = As_lo[mr][kc];
                alo[i][1] = As_lo[mr + 8][kc];
                alo[i][2] = As_lo[mr][kc + 4];
                alo[i][3] = As_lo[mr + 8][kc + 4];
            }
#pragma unroll
            for (int j = 0; j < 8; j++) {
                int kb = kk + (lane & 3);
                int nb = warp_n * 64 + j * 8 + (lane >> 2);
                uint32_t bhi0 = Bs_hi[kb][nb];
                uint32_t bhi1 = Bs_hi[kb + 4][nb];
                uint32_t blo0 = Bs_lo[kb][nb];
                uint32_t blo1 = Bs_lo[kb + 4][nb];
#pragma unroll
                for (int i = 0; i < 2; i++) {
                    float* d = acc[i][j];
                    mma_tf32(d[0], d[1], d[2], d[3],
                             ahi[i][0], ahi[i][1], ahi[i][2], ahi[i][3], bhi0, bhi1);
                    mma_tf32(d[0], d[1], d[2], d[3],
                             ahi[i][0], ahi[i][1], ahi[i][2], ahi[i][3], blo0, blo1);
                    mma_tf32(d[0], d[1], d[2], d[3],
                             alo[i][0], alo[i][1], alo[i][2], alo[i][3], bhi0, bhi1);
                }
            }
        }
        __syncthreads();
    }

    // epilogue: bias + optional relu, guarded stores
#pragma unroll
    for (int i = 0; i < 2; i++) {
        int r0 = rowBase + warp_m * 32 + i * 16 + (lane >> 2);
#pragma unroll
        for (int j = 0; j < 8; j++) {
            int c0 = colBase + warp_n * 64 + j * 8 + (lane & 3) * 2;
            float b0v = bias[c0];
            float b1v = bias[c0 + 1];
            float v0 = acc[i][j][0] + b0v;
            float v1 = acc[i][j][1] + b1v;
            float v2 = acc[i][j][2] + b0v;
            float v3 = acc[i][j][3] + b1v;
            if (doRelu) {
                v0 = fmaxf(v0, 0.f); v1 = fmaxf(v1, 0.f);
                v2 = fmaxf(v2, 0.f); v3 = fmaxf(v3, 0.f);
            }
            if (r0 < Nrows) {
                C[(size_t)r0 * M + c0] = v0;
                C[(size_t)r0 * M + c0 + 1] = v1;
            }
            if (r0 + 8 < Nrows) {
                C[(size_t)(r0 + 8) * M + c0] = v2;
                C[(size_t)(r0 + 8) * M + c0 + 1] = v3;
            }
        }
    }
}

// ---------------- graph mean-pool: sums/counts ----------------
__global__ void __launch_bounds__(192) pool_kernel(
    const int* __restrict__ batch, const float* __restrict__ h,
    float* __restrict__ sums, float* __restrict__ cnt)
{
    const int n = blockIdx.x;
    const int b = batch[n];
    const int f = threadIdx.x;
    float4 v = *(const float4*)(h + (size_t)n * EMB + f * 4);
    float* s = sums + (size_t)b * EMB + f * 4;
    atomicAdd(s + 0, v.x);
    atomicAdd(s + 1, v.y);
    atomicAdd(s + 2, v.z);
    atomicAdd(s + 3, v.w);
    if (f == 0) atomicAdd(&cnt[b], 1.0f);
}

// ---------------- head: mean, dense, log_softmax ----------------
__global__ void __launch_bounds__(192) head_kernel(
    const float* __restrict__ sums, const float* __restrict__ cnt,
    const float* __restrict__ W, const float* __restrict__ bias,
    float* __restrict__ out)
{
    __shared__ float red[192][4];
    const int g = blockIdx.x;
    const int t = threadIdx.x;
    const float c = fmaxf(cnt[g], 1.f);
    float4 p = *(const float4*)(sums + (size_t)g * EMB + t * 4);
    const float inv = 1.f / c;
    p.x *= inv; p.y *= inv; p.z *= inv; p.w *= inv;
    const int f = t * 4;
#pragma unroll
    for (int o = 0; o < 4; o++) {
        red[t][o] = p.x * W[(f + 0) * 4 + o] + p.y * W[(f + 1) * 4 + o] +
                    p.z * W[(f + 2) * 4 + o] + p.w * W[(f + 3) * 4 + o];
    }
    __syncthreads();
    if (t == 0) {
        float l[4];
#pragma unroll
        for (int o = 0; o < 4; o++) {
            float s = bias[o];
            for (int i = 0; i < 192; i++) s += red[i][o];
            l[o] = s;
        }
        float m = fmaxf(fmaxf(l[0], l[1]), fmaxf(l[2], l[3]));
        float se = expf(l[0] - m) + expf(l[1] - m) + expf(l[2] - m) + expf(l[3] - m);
        float lse = m + logf(se);
#pragma unroll
        for (int o = 0; o < 4; o++) out[g * 4 + o] = l[o] - lse;
    }
}

// ---------------- launch ----------------
extern "C" void kernel_launch(void* const* d_in, const int* in_sizes, int n_in,
                              void* d_out, int out_size)
{
    const float* x       = (const float*)d_in[0];
    const int*   ei      = (const int*)d_in[1];
    const int*   batch   = (const int*)d_in[2];
    const float* conv0_w = (const float*)d_in[3];
    const float* bn0_g   = (const float*)d_in[4];
    const float* bn0_b   = (const float*)d_in[5];
    const float* bn0_m   = (const float*)d_in[6];
    const float* bn0_v   = (const float*)d_in[7];
    const float* conv1_w = (const float*)d_in[8];
    const float* conv2_w = (const float*)d_in[9];
    const float* bn2_g   = (const float*)d_in[10];
    const float* bn2_b   = (const float*)d_in[11];
    const float* bn2_m   = (const float*)d_in[12];
    const float* bn2_v   = (const float*)d_in[13];
    const float* g1w1    = (const float*)d_in[14];
    const float* g1b1    = (const float*)d_in[15];
    const float* g1w2    = (const float*)d_in[16];
    const float* g1b2    = (const float*)d_in[17];
    const float* g2w1    = (const float*)d_in[18];
    const float* g2b1    = (const float*)d_in[19];
    const float* g2w2    = (const float*)d_in[20];
    const float* g2b2    = (const float*)d_in[21];
    const float* dW      = (const float*)d_in[22];
    const float* dB      = (const float*)d_in[23];
    float* out = (float*)d_out;

    float *p_h0, *p_agg1, *p_z, *p_h1, *p_agg2, *p_h2, *p_sums, *p_cnt;
    cudaGetSymbolAddress((void**)&p_h0,   g_h0);
    cudaGetSymbolAddress((void**)&p_agg1, g_agg1);
    cudaGetSymbolAddress((void**)&p_z,    g_z);
    cudaGetSymbolAddress((void**)&p_h1,   g_h1);
    cudaGetSymbolAddress((void**)&p_agg2, g_agg2);
    cudaGetSymbolAddress((void**)&p_h2,   g_h2);
    cudaGetSymbolAddress((void**)&p_sums, g_sums);
    cudaGetSymbolAddress((void**)&p_cnt,  g_cnt);

    const dim3 gemmGrid(EMB / BN, (Nn + BM - 1) / BM);

    // 1) temporal conv stack -> h0 (N x 512)
    conv_kernel<<<Nn, 256>>>(x, conv0_w, bn0_g, bn0_b, bn0_m, bn0_v,
                             conv1_w, conv2_w, bn2_g, bn2_b, bn2_m, bn2_v, p_h0);

    // 2) GIN1 aggregation
    {
        int n4 = Nn * FIN / 4;
        zero_kernel<<<(n4 + 255) / 256, 256>>>((float4*)p_agg1, n4);
        edge_agg_kernel<FIN><<<Ee, FIN / 4>>>(ei, p_h0, p_agg1);
    }
    // 3) z1 = relu((h0+agg1)@W1 + b1), h1 = relu(z1@W2 + b2)
    gemm_tc_kernel<true><<<gemmGrid, 256>>>(p_h0, p_agg1, g1w1, g1b1, p_z, Nn, FIN, EMB, 1);
    gemm_tc_kernel<false><<<gemmGrid, 256>>>(p_z, nullptr, g1w2, g1b2, p_h1, Nn, EMB, EMB, 1);

    // 4) GIN2 aggregation
    {
        int n4 = Nn * EMB / 4;
        zero_kernel<<<(n4 + 255) / 256, 256>>>((float4*)p_agg2, n4);
        edge_agg_kernel<EMB><<<Ee, EMB / 4>>>(ei, p_h1, p_agg2);
    }
    // 5) z2 = relu((h1+agg2)@W3 + b3), h2 = relu(z2@W4 + b4)
    gemm_tc_kernel<true><<<gemmGrid, 256>>>(p_h1, p_agg2, g2w1, g2b1, p_z, Nn, EMB, EMB, 1);
    gemm_tc_kernel<false><<<gemmGrid, 256>>>(p_z, nullptr, g2w2, g2b2, p_h2, Nn, EMB, EMB, 1);

    // 6) graph mean pool + dense + log_softmax
    {
        int n4s = Gg * EMB / 4;
        zero_kernel<<<(n4s + 255) / 256, 256>>>((float4*)p_sums, n4s);
        zero_kernel<<<1, 256>>>((float4*)p_cnt, Gg / 4);
        pool_kernel<<<Nn, EMB / 4>>>(batch, p_h2, p_sums, p_cnt);
        head_kernel<<<Gg, EMB / 4>>>(p_sums, p_cnt, dW, dB, out);
    }
}

// round 6
// speedup vs baseline: 1.7757x; 1.5366x over previous
#include <cuda_runtime.h>
#include <cuda_bf16.h>
#include <math.h>
#include <stdint.h>

#define Nn 20000
#define Tt 256
#define Ee 320000
#define Gg 64
#define CT 8
#define CP 16
#define EMB 768
#define OUTC 4
#define FIN 512
#define BN_EPS 1e-5f

// ---------------- scratch (device globals, no allocation) ----------------
__device__ float g_h0[(size_t)Nn * FIN];
__device__ float g_agg1[(size_t)Nn * FIN];
__device__ float g_z[(size_t)Nn * EMB];
__device__ float g_h1[(size_t)Nn * EMB];
__device__ float g_agg2[(size_t)Nn * EMB];
__device__ float g_h2[(size_t)Nn * EMB];
__device__ float g_sums[Gg * EMB];
__device__ float g_cnt[Gg];

// packed bf16 hi/mid weight buffers: layout [K/2][M] uint32 (pair along k)
// sizes (uint32): w1: 256*768=196608, w2/w3/w4: 384*768=294912 each
#define WO1 0
#define WO2 196608
#define WO3 491520
#define WO4 786432
#define WTOT 1081344
__device__ uint32_t g_wh[WTOT];
__device__ uint32_t g_wm[WTOT];

// ---------------- fused temporal conv + BN + pool ----------------
__global__ void __launch_bounds__(256) conv_kernel(
    const float* __restrict__ x,
    const float* __restrict__ w0,
    const float* __restrict__ g0, const float* __restrict__ b0,
    const float* __restrict__ m0, const float* __restrict__ v0,
    const float* __restrict__ w1,
    const float* __restrict__ w2,
    const float* __restrict__ g2, const float* __restrict__ b2,
    const float* __restrict__ m2, const float* __restrict__ v2,
    float* __restrict__ hout)
{
    __shared__ float xs[256];
    __shared__ float w0s[33 * 8];
    __shared__ float w1s[21 * 8];
    __shared__ float w2s[8 * 16];
    __shared__ float sc0[8], sh0[8], sc2[16], sh2[16];
    __shared__ float s1s[8][264];

    const int t = threadIdx.x;
    const int n = blockIdx.x;

    xs[t] = x[(size_t)n * Tt + t];
    for (int i = t; i < 33 * 8; i += 256) w0s[i] = w0[i];
    if (t < 21 * 8) w1s[t] = w1[t];
    if (t < 8 * 16) w2s[t] = w2[t];
    if (t < 8)  { float s = g0[t] * rsqrtf(v0[t] + BN_EPS); sc0[t] = s; sh0[t] = b0[t] - m0[t] * s; }
    if (t < 16) { float s = g2[t] * rsqrtf(v2[t] + BN_EPS); sc2[t] = s; sh2[t] = b2[t] - m2[t] * s; }
    __syncthreads();

    float acc[8];
#pragma unroll
    for (int c = 0; c < 8; c++) acc[c] = 0.f;
#pragma unroll
    for (int w = 0; w < 33; w++) {
        int tt = t + w - 16;
        float xv = (tt >= 0 && tt < 256) ? xs[tt] : 0.f;
#pragma unroll
        for (int c = 0; c < 8; c++) acc[c] += xv * w0s[w * 8 + c];
    }
#pragma unroll
    for (int c = 0; c < 8; c++) s1s[c][t] = acc[c] * sc0[c] + sh0[c];
    __syncthreads();

    float s2[8];
#pragma unroll
    for (int c = 0; c < 8; c++) {
        float a = 0.f;
#pragma unroll
        for (int w = 0; w < 21; w++) {
            int tt = t + w - 10;
            float xv = (tt >= 0 && tt < 256) ? s1s[c][tt] : 0.f;
            a += xv * w1s[w * 8 + c];
        }
        s2[c] = fmaxf(a, 0.f);
    }

    const int lane = t & 31;
#pragma unroll
    for (int o = 0; o < 16; o++) {
        float a = 0.f;
#pragma unroll
        for (int c = 0; c < 8; c++) a += s2[c] * w2s[c * 16 + o];
        a = fmaxf(a * sc2[o] + sh2[o], 0.f);
        a += __shfl_xor_sync(0xffffffffu, a, 1);
        a += __shfl_xor_sync(0xffffffffu, a, 2);
        a += __shfl_xor_sync(0xffffffffu, a, 4);
        if ((lane & 7) == 0)
            hout[(size_t)n * FIN + (t >> 3) * 16 + o] = a * 0.125f;
    }
}

// ---------------- utility: zero buffer (float4) ----------------
__global__ void zero_kernel(float4* __restrict__ p, int n4)
{
    int i = blockIdx.x * blockDim.x + threadIdx.x;
    int stride = gridDim.x * blockDim.x;
    float4 z = make_float4(0.f, 0.f, 0.f, 0.f);
    for (; i < n4; i += stride) p[i] = z;
}

// ---------------- weight prep: fp32 [K][M] -> packed bf16 hi/mid [K/2][M] ----
__global__ void __launch_bounds__(256) wprep_kernel(
    const float* __restrict__ W, uint32_t* __restrict__ Wh, uint32_t* __restrict__ Wm,
    int total, int M)
{
    int idx = blockIdx.x * blockDim.x + threadIdx.x;
    if (idx >= total) return;
    int kp = idx / M, n = idx - kp * M;
    float f0 = W[(size_t)(2 * kp) * M + n];
    float f1 = W[(size_t)(2 * kp + 1) * M + n];
    __nv_bfloat162 bh = __floats2bfloat162_rn(f0, f1);
    float r0 = f0 - __bfloat162float(bh.x);
    float r1 = f1 - __bfloat162float(bh.y);
    __nv_bfloat162 bm = __floats2bfloat162_rn(r0, r1);
    Wh[idx] = *(uint32_t*)&bh;
    Wm[idx] = *(uint32_t*)&bm;
}

// ---------------- edge aggregation: agg[dst] += h[src] (red.v4) ----------------
template <int F>
__global__ void __launch_bounds__(F / 4) edge_agg_kernel(
    const int* __restrict__ ei, const float* __restrict__ h, float* __restrict__ agg)
{
    const int e = blockIdx.x;
    const int src = __ldg(ei + e);
    const int dst = __ldg(ei + Ee + e);
    const int f = threadIdx.x;
    float4 v = __ldg((const float4*)(h + (size_t)src * F) + f);
    float* a = agg + (size_t)dst * F + f * 4;
    asm volatile("red.global.add.v4.f32 [%0], {%1,%2,%3,%4};"
                 :: "l"(a), "f"(v.x), "f"(v.y), "f"(v.z), "f"(v.w) : "memory");
}

// ---------------- bf16 4-pass tensor-core GEMM --------------------------------
// C = act((A [+A2]) @ B + bias); A: Nrows x K fp32 row-major.
// B pre-split: Bh/Bm packed bf16 pairs, layout [K/2][M] uint32.
// Block tile 128x128, BK=32, 256 threads, warps 4(m) x 2(n), warp tile 32x64.
#define BM 128
#define BN 128
#define BK 32
#define KP 16          // pairs per k-tile
#define AS_STRIDE 20   // KP + 4
#define BS_STRIDE 136  // BN + 8

__device__ __forceinline__ void mma_bf16(
    float* d, const uint32_t* a, uint32_t b0, uint32_t b1)
{
    asm volatile(
        "mma.sync.aligned.m16n8k16.row.col.f32.bf16.bf16.f32 "
        "{%0,%1,%2,%3}, {%4,%5,%6,%7}, {%8,%9}, {%0,%1,%2,%3};"
        : "+f"(d[0]), "+f"(d[1]), "+f"(d[2]), "+f"(d[3])
        : "r"(a[0]), "r"(a[1]), "r"(a[2]), "r"(a[3]), "r"(b0), "r"(b1));
}

template <bool ADD>
__global__ void __launch_bounds__(256) gemm_bf16_kernel(
    const float* __restrict__ A, const float* __restrict__ A2,
    const uint32_t* __restrict__ Bh, const uint32_t* __restrict__ Bm,
    const float* __restrict__ bias,
    float* __restrict__ C, int Nrows, int K, int M, int doRelu)
{
    __shared__ uint32_t As_h[BM][AS_STRIDE];
    __shared__ uint32_t As_m[BM][AS_STRIDE];
    __shared__ uint32_t Bs_h[KP][BS_STRIDE];
    __shared__ uint32_t Bs_m[KP][BS_STRIDE];

    const int tid = threadIdx.x;
    const int lane = tid & 31;
    const int warp = tid >> 5;
    const int warp_m = warp & 3;
    const int warp_n = warp >> 2;
    const int rowBase = blockIdx.y * BM;
    const int colBase = blockIdx.x * BN;

    // A staging: thread handles rows r0, r0+64 at k-floats c4*8..c4*8+7
    const int r0 = tid >> 2;      // 0..63
    const int c4 = tid & 3;       // 0..3
    // B staging: thread handles kpairs kp0, kp0+8 at n = n4*4..n4*4+3
    const int kp0 = tid >> 5;     // 0..7
    const int n4 = tid & 31;      // 0..31

    float acc[2][8][4];
#pragma unroll
    for (int i = 0; i < 2; i++)
#pragma unroll
        for (int j = 0; j < 8; j++)
#pragma unroll
            for (int r = 0; r < 4; r++) acc[i][j][r] = 0.f;

    float aF[2][8];
    uint4 bHreg[2], bMreg[2];

    // ---- prefetch k0 = 0 ----
    {
#pragma unroll
        for (int h = 0; h < 2; h++) {
            int r = rowBase + r0 + h * 64;
            if (r < Nrows) {
                float4 u = *(const float4*)(A + (size_t)r * K + c4 * 8);
                float4 v = *(const float4*)(A + (size_t)r * K + c4 * 8 + 4);
                if (ADD) {
                    float4 u2 = *(const float4*)(A2 + (size_t)r * K + c4 * 8);
                    float4 v2 = *(const float4*)(A2 + (size_t)r * K + c4 * 8 + 4);
                    u.x += u2.x; u.y += u2.y; u.z += u2.z; u.w += u2.w;
                    v.x += v2.x; v.y += v2.y; v.z += v2.z; v.w += v2.w;
                }
                aF[h][0] = u.x; aF[h][1] = u.y; aF[h][2] = u.z; aF[h][3] = u.w;
                aF[h][4] = v.x; aF[h][5] = v.y; aF[h][6] = v.z; aF[h][7] = v.w;
            } else {
#pragma unroll
                for (int q = 0; q < 8; q++) aF[h][q] = 0.f;
            }
        }
#pragma unroll
        for (int h = 0; h < 2; h++) {
            size_t off = (size_t)(kp0 + h * 8) * M + colBase + n4 * 4;
            bHreg[h] = *(const uint4*)(Bh + off);
            bMreg[h] = *(const uint4*)(Bm + off);
        }
    }

    for (int k0 = 0; k0 < K; k0 += BK) {
        // ---- convert + store staged data to smem ----
#pragma unroll
        for (int h = 0; h < 2; h++) {
            int row = r0 + h * 64;
            uint32_t hi[4], mi[4];
#pragma unroll
            for (int p = 0; p < 4; p++) {
                float f0 = aF[h][2 * p], f1 = aF[h][2 * p + 1];
                __nv_bfloat162 bh = __floats2bfloat162_rn(f0, f1);
                float rr0 = f0 - __bfloat162float(bh.x);
                float rr1 = f1 - __bfloat162float(bh.y);
                __nv_bfloat162 bm = __floats2bfloat162_rn(rr0, rr1);
                hi[p] = *(uint32_t*)&bh;
                mi[p] = *(uint32_t*)&bm;
            }
            *(uint4*)&As_h[row][c4 * 4] = make_uint4(hi[0], hi[1], hi[2], hi[3]);
            *(uint4*)&As_m[row][c4 * 4] = make_uint4(mi[0], mi[1], mi[2], mi[3]);
        }
#pragma unroll
        for (int h = 0; h < 2; h++) {
            *(uint4*)&Bs_h[kp0 + h * 8][n4 * 4] = bHreg[h];
            *(uint4*)&Bs_m[kp0 + h * 8][n4 * 4] = bMreg[h];
        }
        __syncthreads();

        // ---- prefetch next ----
        if (k0 + BK < K) {
            const int kn = k0 + BK;
#pragma unroll
            for (int h = 0; h < 2; h++) {
                int r = rowBase + r0 + h * 64;
                if (r < Nrows) {
                    float4 u = *(const float4*)(A + (size_t)r * K + kn + c4 * 8);
                    float4 v = *(const float4*)(A + (size_t)r * K + kn + c4 * 8 + 4);
                    if (ADD) {
                        float4 u2 = *(const float4*)(A2 + (size_t)r * K + kn + c4 * 8);
                        float4 v2 = *(const float4*)(A2 + (size_t)r * K + kn + c4 * 8 + 4);
                        u.x += u2.x; u.y += u2.y; u.z += u2.z; u.w += u2.w;
                        v.x += v2.x; v.y += v2.y; v.z += v2.z; v.w += v2.w;
                    }
                    aF[h][0] = u.x; aF[h][1] = u.y; aF[h][2] = u.z; aF[h][3] = u.w;
                    aF[h][4] = v.x; aF[h][5] = v.y; aF[h][6] = v.z; aF[h][7] = v.w;
                } else {
#pragma unroll
                    for (int q = 0; q < 8; q++) aF[h][q] = 0.f;
                }
            }
#pragma unroll
            for (int h = 0; h < 2; h++) {
                size_t off = (size_t)(kn / 2 + kp0 + h * 8) * M + colBase + n4 * 4;
                bHreg[h] = *(const uint4*)(Bh + off);
                bMreg[h] = *(const uint4*)(Bm + off);
            }
        }

        // ---- compute: 2 k16 steps ----
#pragma unroll
        for (int step = 0; step < 2; step++) {
            const int koff = step * 8;
            uint32_t ah[2][4], am[2][4];
#pragma unroll
            for (int i = 0; i < 2; i++) {
                int mr = warp_m * 32 + i * 16 + (lane >> 2);
                int kc = koff + (lane & 3);
                ah[i][0] = As_h[mr][kc];
                ah[i][1] = As_h[mr + 8][kc];
                ah[i][2] = As_h[mr][kc + 4];
                ah[i][3] = As_h[mr + 8][kc + 4];
                am[i][0] = As_m[mr][kc];
                am[i][1] = As_m[mr + 8][kc];
                am[i][2] = As_m[mr][kc + 4];
                am[i][3] = As_m[mr + 8][kc + 4];
            }
#pragma unroll
            for (int j = 0; j < 8; j++) {
                int kb = koff + (lane & 3);
                int nb = warp_n * 64 + j * 8 + (lane >> 2);
                uint32_t bh0 = Bs_h[kb][nb];
                uint32_t bh1 = Bs_h[kb + 4][nb];
                uint32_t bm0 = Bs_m[kb][nb];
                uint32_t bm1 = Bs_m[kb + 4][nb];
#pragma unroll
                for (int i = 0; i < 2; i++) {
                    mma_bf16(acc[i][j], ah[i], bh0, bh1);
                    mma_bf16(acc[i][j], ah[i], bm0, bm1);
                    mma_bf16(acc[i][j], am[i], bh0, bh1);
                    mma_bf16(acc[i][j], am[i], bm0, bm1);
                }
            }
        }
        __syncthreads();
    }

    // ---- epilogue ----
#pragma unroll
    for (int i = 0; i < 2; i++) {
        int r = rowBase + warp_m * 32 + i * 16 + (lane >> 2);
#pragma unroll
        for (int j = 0; j < 8; j++) {
            int c0 = colBase + warp_n * 64 + j * 8 + (lane & 3) * 2;
            float b0v = bias[c0];
            float b1v = bias[c0 + 1];
            float v0 = acc[i][j][0] + b0v;
            float v1 = acc[i][j][1] + b1v;
            float v2 = acc[i][j][2] + b0v;
            float v3 = acc[i][j][3] + b1v;
            if (doRelu) {
                v0 = fmaxf(v0, 0.f); v1 = fmaxf(v1, 0.f);
                v2 = fmaxf(v2, 0.f); v3 = fmaxf(v3, 0.f);
            }
            if (r < Nrows) {
                C[(size_t)r * M + c0] = v0;
                C[(size_t)r * M + c0 + 1] = v1;
            }
            if (r + 8 < Nrows) {
                C[(size_t)(r + 8) * M + c0] = v2;
                C[(size_t)(r + 8) * M + c0 + 1] = v3;
            }
        }
    }
}

// ---------------- graph mean-pool: sums/counts (red.v4) ----------------
__global__ void __launch_bounds__(192) pool_kernel(
    const int* __restrict__ batch, const float* __restrict__ h,
    float* __restrict__ sums, float* __restrict__ cnt)
{
    const int n = blockIdx.x;
    const int b = __ldg(batch + n);
    const int f = threadIdx.x;
    float4 v = __ldg((const float4*)(h + (size_t)n * EMB) + f);
    float* s = sums + (size_t)b * EMB + f * 4;
    asm volatile("red.global.add.v4.f32 [%0], {%1,%2,%3,%4};"
                 :: "l"(s), "f"(v.x), "f"(v.y), "f"(v.z), "f"(v.w) : "memory");
    if (f == 0) atomicAdd(&cnt[b], 1.0f);
}

// ---------------- head: mean, dense, log_softmax ----------------
__global__ void __launch_bounds__(192) head_kernel(
    const float* __restrict__ sums, const float* __restrict__ cnt,
    const float* __restrict__ W, const float* __restrict__ bias,
    float* __restrict__ out)
{
    __shared__ float red[192][4];
    const int g = blockIdx.x;
    const int t = threadIdx.x;
    const float c = fmaxf(cnt[g], 1.f);
    float4 p = *(const float4*)(sums + (size_t)g * EMB + t * 4);
    const float inv = 1.f / c;
    p.x *= inv; p.y *= inv; p.z *= inv; p.w *= inv;
    const int f = t * 4;
#pragma unroll
    for (int o = 0; o < 4; o++) {
        red[t][o] = p.x * W[(f + 0) * 4 + o] + p.y * W[(f + 1) * 4 + o] +
                    p.z * W[(f + 2) * 4 + o] + p.w * W[(f + 3) * 4 + o];
    }
    __syncthreads();
    if (t == 0) {
        float l[4];
#pragma unroll
        for (int o = 0; o < 4; o++) {
            float s = bias[o];
            for (int i = 0; i < 192; i++) s += red[i][o];
            l[o] = s;
        }
        float m = fmaxf(fmaxf(l[0], l[1]), fmaxf(l[2], l[3]));
        float se = expf(l[0] - m) + expf(l[1] - m) + expf(l[2] - m) + expf(l[3] - m);
        float lse = m + logf(se);
#pragma unroll
        for (int o = 0; o < 4; o++) out[g * 4 + o] = l[o] - lse;
    }
}

// ---------------- launch ----------------
extern "C" void kernel_launch(void* const* d_in, const int* in_sizes, int n_in,
                              void* d_out, int out_size)
{
    const float* x       = (const float*)d_in[0];
    const int*   ei      = (const int*)d_in[1];
    const int*   batch   = (const int*)d_in[2];
    const float* conv0_w = (const float*)d_in[3];
    const float* bn0_g   = (const float*)d_in[4];
    const float* bn0_b   = (const float*)d_in[5];
    const float* bn0_m   = (const float*)d_in[6];
    const float* bn0_v   = (const float*)d_in[7];
    const float* conv1_w = (const float*)d_in[8];
    const float* conv2_w = (const float*)d_in[9];
    const float* bn2_g   = (const float*)d_in[10];
    const float* bn2_b   = (const float*)d_in[11];
    const float* bn2_m   = (const float*)d_in[12];
    const float* bn2_v   = (const float*)d_in[13];
    const float* g1w1    = (const float*)d_in[14];
    const float* g1b1    = (const float*)d_in[15];
    const float* g1w2    = (const float*)d_in[16];
    const float* g1b2    = (const float*)d_in[17];
    const float* g2w1    = (const float*)d_in[18];
    const float* g2b1    = (const float*)d_in[19];
    const float* g2w2    = (const float*)d_in[20];
    const float* g2b2    = (const float*)d_in[21];
    const float* dW      = (const float*)d_in[22];
    const float* dB      = (const float*)d_in[23];
    float* out = (float*)d_out;

    float *p_h0, *p_agg1, *p_z, *p_h1, *p_agg2, *p_h2, *p_sums, *p_cnt;
    uint32_t *p_wh, *p_wm;
    cudaGetSymbolAddress((void**)&p_h0,   g_h0);
    cudaGetSymbolAddress((void**)&p_agg1, g_agg1);
    cudaGetSymbolAddress((void**)&p_z,    g_z);
    cudaGetSymbolAddress((void**)&p_h1,   g_h1);
    cudaGetSymbolAddress((void**)&p_agg2, g_agg2);
    cudaGetSymbolAddress((void**)&p_h2,   g_h2);
    cudaGetSymbolAddress((void**)&p_sums, g_sums);
    cudaGetSymbolAddress((void**)&p_cnt,  g_cnt);
    cudaGetSymbolAddress((void**)&p_wh,   g_wh);
    cudaGetSymbolAddress((void**)&p_wm,   g_wm);

    const dim3 gemmGrid(EMB / BN, (Nn + BM - 1) / BM);

    // 0) weight prep (packed bf16 hi/mid splits)
    wprep_kernel<<<(196608 + 255) / 256, 256>>>(g1w1, p_wh + WO1, p_wm + WO1, 196608, EMB);
    wprep_kernel<<<(294912 + 255) / 256, 256>>>(g1w2, p_wh + WO2, p_wm + WO2, 294912, EMB);
    wprep_kernel<<<(294912 + 255) / 256, 256>>>(g2w1, p_wh + WO3, p_wm + WO3, 294912, EMB);
    wprep_kernel<<<(294912 + 255) / 256, 256>>>(g2w2, p_wh + WO4, p_wm + WO4, 294912, EMB);

    // 1) temporal conv stack -> h0 (N x 512)
    conv_kernel<<<Nn, 256>>>(x, conv0_w, bn0_g, bn0_b, bn0_m, bn0_v,
                             conv1_w, conv2_w, bn2_g, bn2_b, bn2_m, bn2_v, p_h0);

    // 2) GIN1 aggregation
    {
        int n4 = Nn * FIN / 4;
        zero_kernel<<<(n4 + 255) / 256, 256>>>((float4*)p_agg1, n4);
        edge_agg_kernel<FIN><<<Ee, FIN / 4>>>(ei, p_h0, p_agg1);
    }
    // 3) z1 = relu((h0+agg1)@W1 + b1), h1 = relu(z1@W2 + b2)
    gemm_bf16_kernel<true><<<gemmGrid, 256>>>(p_h0, p_agg1, p_wh + WO1, p_wm + WO1, g1b1, p_z, Nn, FIN, EMB, 1);
    gemm_bf16_kernel<false><<<gemmGrid, 256>>>(p_z, nullptr, p_wh + WO2, p_wm + WO2, g1b2, p_h1, Nn, EMB, EMB, 1);

    // 4) GIN2 aggregation
    {
        int n4 = Nn * EMB / 4;
        zero_kernel<<<(n4 + 255) / 256, 256>>>((float4*)p_agg2, n4);
        edge_agg_kernel<EMB><<<Ee, EMB / 4>>>(ei, p_h1, p_agg2);
    }
    // 5) z2 = relu((h1+agg2)@W3 + b3), h2 = relu(z2@W4 + b4)
    gemm_bf16_kernel<true><<<gemmGrid, 256>>>(p_h1, p_agg2, p_wh + WO3, p_wm + WO3, g2b1, p_z, Nn, EMB, EMB, 1);
    gemm_bf16_kernel<false><<<gemmGrid, 256>>>(p_z, nullptr, p_wh + WO4, p_wm + WO4, g2b2, p_h2, Nn, EMB, EMB, 1);

    // 6) graph mean pool + dense + log_softmax
    {
        int n4s = Gg * EMB / 4;
        zero_kernel<<<(n4s + 255) / 256, 256>>>((float4*)p_sums, n4s);
        zero_kernel<<<1, 256>>>((float4*)p_cnt, Gg / 4);
        pool_kernel<<<Nn, EMB / 4>>>(batch, p_h2, p_sums, p_cnt);
        head_kernel<<<Gg, EMB / 4>>>(p_sums, p_cnt, dW, dB, out);
    }
}

// round 8
// speedup vs baseline: 2.1801x; 1.2278x over previous
#include <cuda_runtime.h>
#include <cuda_bf16.h>
#include <math.h>
#include <stdint.h>

#define Nn 20000
#define Tt 256
#define Ee 320000
#define Gg 64
#define CT 8
#define CP 16
#define EMB 768
#define OUTC 4
#define FIN 512
#define BN_EPS 1e-5f

// ---------------- scratch (device globals, no allocation) ----------------
__device__ float g_h0[(size_t)Nn * FIN];
__device__ float g_agg1[(size_t)Nn * FIN];
__device__ float g_z[(size_t)Nn * EMB];
__device__ float g_h1[(size_t)Nn * EMB];
__device__ float g_agg2[(size_t)Nn * EMB];
__device__ float g_h2[(size_t)Nn * EMB];
__device__ float g_sums[Gg * EMB];
__device__ float g_cnt[Gg];

// packed bf16 hi/mid weight buffers: layout [K/2][M] uint32 (pair along k)
#define WO1 0
#define WO2 196608
#define WO3 491520
#define WO4 786432
#define WTOT 1081344
__device__ uint32_t g_wh[WTOT];
__device__ uint32_t g_wm[WTOT];

// ---------------- fused temporal conv + BN + pool ----------------
__global__ void __launch_bounds__(256) conv_kernel(
    const float* __restrict__ x,
    const float* __restrict__ w0,
    const float* __restrict__ g0, const float* __restrict__ b0,
    const float* __restrict__ m0, const float* __restrict__ v0,
    const float* __restrict__ w1,
    const float* __restrict__ w2,
    const float* __restrict__ g2, const float* __restrict__ b2,
    const float* __restrict__ m2, const float* __restrict__ v2,
    float* __restrict__ hout)
{
    __shared__ float xs[256];
    __shared__ float w0s[33 * 8];
    __shared__ float w1s[21 * 8];
    __shared__ float w2s[8 * 16];
    __shared__ float sc0[8], sh0[8], sc2[16], sh2[16];
    __shared__ float s1s[8][264];

    const int t = threadIdx.x;
    const int n = blockIdx.x;

    xs[t] = x[(size_t)n * Tt + t];
    for (int i = t; i < 33 * 8; i += 256) w0s[i] = w0[i];
    if (t < 21 * 8) w1s[t] = w1[t];
    if (t < 8 * 16) w2s[t] = w2[t];
    if (t < 8)  { float s = g0[t] * rsqrtf(v0[t] + BN_EPS); sc0[t] = s; sh0[t] = b0[t] - m0[t] * s; }
    if (t < 16) { float s = g2[t] * rsqrtf(v2[t] + BN_EPS); sc2[t] = s; sh2[t] = b2[t] - m2[t] * s; }
    __syncthreads();

    float acc[8];
#pragma unroll
    for (int c = 0; c < 8; c++) acc[c] = 0.f;
#pragma unroll
    for (int w = 0; w < 33; w++) {
        int tt = t + w - 16;
        float xv = (tt >= 0 && tt < 256) ? xs[tt] : 0.f;
#pragma unroll
        for (int c = 0; c < 8; c++) acc[c] += xv * w0s[w * 8 + c];
    }
#pragma unroll
    for (int c = 0; c < 8; c++) s1s[c][t] = acc[c] * sc0[c] + sh0[c];
    __syncthreads();

    float s2[8];
#pragma unroll
    for (int c = 0; c < 8; c++) {
        float a = 0.f;
#pragma unroll
        for (int w = 0; w < 21; w++) {
            int tt = t + w - 10;
            float xv = (tt >= 0 && tt < 256) ? s1s[c][tt] : 0.f;
            a += xv * w1s[w * 8 + c];
        }
        s2[c] = fmaxf(a, 0.f);
    }

    const int lane = t & 31;
#pragma unroll
    for (int o = 0; o < 16; o++) {
        float a = 0.f;
#pragma unroll
        for (int c = 0; c < 8; c++) a += s2[c] * w2s[c * 16 + o];
        a = fmaxf(a * sc2[o] + sh2[o], 0.f);
        a += __shfl_xor_sync(0xffffffffu, a, 1);
        a += __shfl_xor_sync(0xffffffffu, a, 2);
        a += __shfl_xor_sync(0xffffffffu, a, 4);
        if ((lane & 7) == 0)
            hout[(size_t)n * FIN + (t >> 3) * 16 + o] = a * 0.125f;
    }
}

// ---------------- utility kernels ----------------
__global__ void zero_kernel(float4* __restrict__ p, int n4)
{
    int i = blockIdx.x * blockDim.x + threadIdx.x;
    int stride = gridDim.x * blockDim.x;
    float4 z = make_float4(0.f, 0.f, 0.f, 0.f);
    for (; i < n4; i += stride) p[i] = z;
}

// copy h -> agg (initializes aggregation with self term; edges add on top)
__global__ void copy_kernel(const float4* __restrict__ src, float4* __restrict__ dst, int n4)
{
    int i = blockIdx.x * blockDim.x + threadIdx.x;
    int stride = gridDim.x * blockDim.x;
    for (; i < n4; i += stride) dst[i] = src[i];
}

// ---------------- weight prep: fp32 [K][M] -> packed bf16 hi/mid [K/2][M] ----
__global__ void __launch_bounds__(256) wprep_kernel(
    const float* __restrict__ W, uint32_t* __restrict__ Wh, uint32_t* __restrict__ Wm,
    int total, int M)
{
    int idx = blockIdx.x * blockDim.x + threadIdx.x;
    if (idx >= total) return;
    int kp = idx / M, n = idx - kp * M;
    float f0 = W[(size_t)(2 * kp) * M + n];
    float f1 = W[(size_t)(2 * kp + 1) * M + n];
    __nv_bfloat162 bh = __floats2bfloat162_rn(f0, f1);
    float r0 = f0 - __bfloat162float(bh.x);
    float r1 = f1 - __bfloat162float(bh.y);
    __nv_bfloat162 bm = __floats2bfloat162_rn(r0, r1);
    Wh[idx] = *(uint32_t*)&bh;
    Wm[idx] = *(uint32_t*)&bm;
}

// ---------------- edge aggregation: agg[dst] += h[src] (red.v4) ----------------
template <int F>
__global__ void __launch_bounds__(F / 4) edge_agg_kernel(
    const int* __restrict__ ei, const float* __restrict__ h, float* __restrict__ agg)
{
    const int e = blockIdx.x;
    const int src = __ldg(ei + e);
    const int dst = __ldg(ei + Ee + e);
    const int f = threadIdx.x;
    float4 v = __ldg((const float4*)(h + (size_t)src * F) + f);
    float* a = agg + (size_t)dst * F + f * 4;
    asm volatile("red.global.add.v4.f32 [%0], {%1,%2,%3,%4};"
                 :: "l"(a), "f"(v.x), "f"(v.y), "f"(v.z), "f"(v.w) : "memory");
}

// ---------------- bf16 3-pass tensor-core GEMM --------------------------------
// C = act(A @ B + bias); A: Nrows x K fp32 row-major (split to bf16 hi/mid in-kernel).
// B pre-split: Bh/Bm packed bf16 pairs, layout [K/2][M] uint32.
// Block tile 128x128, BK=32, 256 threads, warps 4(m) x 2(n), warp tile 32x64.
#define BM 128
#define BN 128
#define BK 32
#define KP 16          // pairs per k-tile
#define AS_STRIDE 20   // KP + 4
#define BS_STRIDE 136  // BN + 8

__device__ __forceinline__ void mma_bf16(
    float* d, const uint32_t* a, uint32_t b0, uint32_t b1)
{
    asm volatile(
        "mma.sync.aligned.m16n8k16.row.col.f32.bf16.bf16.f32 "
        "{%0,%1,%2,%3}, {%4,%5,%6,%7}, {%8,%9}, {%0,%1,%2,%3};"
        : "+f"(d[0]), "+f"(d[1]), "+f"(d[2]), "+f"(d[3])
        : "r"(a[0]), "r"(a[1]), "r"(a[2]), "r"(a[3]), "r"(b0), "r"(b1));
}

__global__ void __launch_bounds__(256, 2) gemm_bf16_kernel(
    const float* __restrict__ A,
    const uint32_t* __restrict__ Bh, const uint32_t* __restrict__ Bm,
    const float* __restrict__ bias,
    float* __restrict__ C, int Nrows, int K, int M, int doRelu)
{
    __shared__ uint32_t As_h[BM][AS_STRIDE];
    __shared__ uint32_t As_m[BM][AS_STRIDE];
    __shared__ uint32_t Bs_h[KP][BS_STRIDE];
    __shared__ uint32_t Bs_m[KP][BS_STRIDE];

    const int tid = threadIdx.x;
    const int lane = tid & 31;
    const int warp = tid >> 5;
    const int warp_m = warp & 3;
    const int warp_n = warp >> 2;
    const int rowBase = blockIdx.y * BM;
    const int colBase = blockIdx.x * BN;

    const int r0 = tid >> 2;      // 0..63 (rows r0, r0+64)
    const int c4 = tid & 3;       // 0..3 (k-floats c4*8..+7)
    const int kp0 = tid >> 5;     // 0..7 (kpairs kp0, kp0+8)
    const int n4 = tid & 31;      // 0..31 (n = n4*4..+3)

    float acc[2][8][4];
#pragma unroll
    for (int i = 0; i < 2; i++)
#pragma unroll
        for (int j = 0; j < 8; j++)
#pragma unroll
            for (int r = 0; r < 4; r++) acc[i][j][r] = 0.f;

    float aF[2][8];
    uint4 bHreg[2], bMreg[2];

    // ---- prefetch k0 = 0 ----
    {
#pragma unroll
        for (int h = 0; h < 2; h++) {
            int r = rowBase + r0 + h * 64;
            if (r < Nrows) {
                float4 u = *(const float4*)(A + (size_t)r * K + c4 * 8);
                float4 v = *(const float4*)(A + (size_t)r * K + c4 * 8 + 4);
                aF[h][0] = u.x; aF[h][1] = u.y; aF[h][2] = u.z; aF[h][3] = u.w;
                aF[h][4] = v.x; aF[h][5] = v.y; aF[h][6] = v.z; aF[h][7] = v.w;
            } else {
#pragma unroll
                for (int q = 0; q < 8; q++) aF[h][q] = 0.f;
            }
        }
#pragma unroll
        for (int h = 0; h < 2; h++) {
            size_t off = (size_t)(kp0 + h * 8) * M + colBase + n4 * 4;
            bHreg[h] = *(const uint4*)(Bh + off);
            bMreg[h] = *(const uint4*)(Bm + off);
        }
    }

    for (int k0 = 0; k0 < K; k0 += BK) {
        // ---- convert + store staged data to smem ----
#pragma unroll
        for (int h = 0; h < 2; h++) {
            int row = r0 + h * 64;
            uint32_t hi[4], mi[4];
#pragma unroll
            for (int p = 0; p < 4; p++) {
                float f0 = aF[h][2 * p], f1 = aF[h][2 * p + 1];
                __nv_bfloat162 bh = __floats2bfloat162_rn(f0, f1);
                float rr0 = f0 - __bfloat162float(bh.x);
                float rr1 = f1 - __bfloat162float(bh.y);
                __nv_bfloat162 bm = __floats2bfloat162_rn(rr0, rr1);
                hi[p] = *(uint32_t*)&bh;
                mi[p] = *(uint32_t*)&bm;
            }
            *(uint4*)&As_h[row][c4 * 4] = make_uint4(hi[0], hi[1], hi[2], hi[3]);
            *(uint4*)&As_m[row][c4 * 4] = make_uint4(mi[0], mi[1], mi[2], mi[3]);
        }
#pragma unroll
        for (int h = 0; h < 2; h++) {
            *(uint4*)&Bs_h[kp0 + h * 8][n4 * 4] = bHreg[h];
            *(uint4*)&Bs_m[kp0 + h * 8][n4 * 4] = bMreg[h];
        }
        __syncthreads();

        // ---- prefetch next ----
        if (k0 + BK < K) {
            const int kn = k0 + BK;
#pragma unroll
            for (int h = 0; h < 2; h++) {
                int r = rowBase + r0 + h * 64;
                if (r < Nrows) {
                    float4 u = *(const float4*)(A + (size_t)r * K + kn + c4 * 8);
                    float4 v = *(const float4*)(A + (size_t)r * K + kn + c4 * 8 + 4);
                    aF[h][0] = u.x; aF[h][1] = u.y; aF[h][2] = u.z; aF[h][3] = u.w;
                    aF[h][4] = v.x; aF[h][5] = v.y; aF[h][6] = v.z; aF[h][7] = v.w;
                } else {
#pragma unroll
                    for (int q = 0; q < 8; q++) aF[h][q] = 0.f;
                }
            }
#pragma unroll
            for (int h = 0; h < 2; h++) {
                size_t off = (size_t)(kn / 2 + kp0 + h * 8) * M + colBase + n4 * 4;
                bHreg[h] = *(const uint4*)(Bh + off);
                bMreg[h] = *(const uint4*)(Bm + off);
            }
        }

        // ---- compute: 2 k16 steps, 3 MMA passes (hh + hm + mh) ----
#pragma unroll
        for (int step = 0; step < 2; step++) {
            const int koff = step * 8;
            uint32_t ah[2][4], am[2][4];
#pragma unroll
            for (int i = 0; i < 2; i++) {
                int mr = warp_m * 32 + i * 16 + (lane >> 2);
                int kc = koff + (lane & 3);
                ah[i][0] = As_h[mr][kc];
                ah[i][1] = As_h[mr + 8][kc];
                ah[i][2] = As_h[mr][kc + 4];
                ah[i][3] = As_h[mr + 8][kc + 4];
                am[i][0] = As_m[mr][kc];
                am[i][1] = As_m[mr + 8][kc];
                am[i][2] = As_m[mr][kc + 4];
                am[i][3] = As_m[mr + 8][kc + 4];
            }
#pragma unroll
            for (int j = 0; j < 8; j++) {
                int kb = koff + (lane & 3);
                int nb = warp_n * 64 + j * 8 + (lane >> 2);
                uint32_t bh0 = Bs_h[kb][nb];
                uint32_t bh1 = Bs_h[kb + 4][nb];
                uint32_t bm0 = Bs_m[kb][nb];
                uint32_t bm1 = Bs_m[kb + 4][nb];
#pragma unroll
                for (int i = 0; i < 2; i++) {
                    mma_bf16(acc[i][j], ah[i], bh0, bh1);
                    mma_bf16(acc[i][j], ah[i], bm0, bm1);
                    mma_bf16(acc[i][j], am[i], bh0, bh1);
                }
            }
        }
        __syncthreads();
    }

    // ---- epilogue ----
#pragma unroll
    for (int i = 0; i < 2; i++) {
        int r = rowBase + warp_m * 32 + i * 16 + (lane >> 2);
#pragma unroll
        for (int j = 0; j < 8; j++) {
            int c0 = colBase + warp_n * 64 + j * 8 + (lane & 3) * 2;
            float b0v = bias[c0];
            float b1v = bias[c0 + 1];
            float v0 = acc[i][j][0] + b0v;
            float v1 = acc[i][j][1] + b1v;
            float v2 = acc[i][j][2] + b0v;
            float v3 = acc[i][j][3] + b1v;
            if (doRelu) {
                v0 = fmaxf(v0, 0.f); v1 = fmaxf(v1, 0.f);
                v2 = fmaxf(v2, 0.f); v3 = fmaxf(v3, 0.f);
            }
            if (r < Nrows) {
                C[(size_t)r * M + c0] = v0;
                C[(size_t)r * M + c0 + 1] = v1;
            }
            if (r + 8 < Nrows) {
                C[(size_t)(r + 8) * M + c0] = v2;
                C[(size_t)(r + 8) * M + c0 + 1] = v3;
            }
        }
    }
}

// ---------------- graph mean-pool: sums/counts (red.v4) ----------------
__global__ void __launch_bounds__(192) pool_kernel(
    const int* __restrict__ batch, const float* __restrict__ h,
    float* __restrict__ sums, float* __restrict__ cnt)
{
    const int n = blockIdx.x;
    const int b = __ldg(batch + n);
    const int f = threadIdx.x;
    float4 v = __ldg((const float4*)(h + (size_t)n * EMB) + f);
    float* s = sums + (size_t)b * EMB + f * 4;
    asm volatile("red.global.add.v4.f32 [%0], {%1,%2,%3,%4};"
                 :: "l"(s), "f"(v.x), "f"(v.y), "f"(v.z), "f"(v.w) : "memory");
    if (f == 0) atomicAdd(&cnt[b], 1.0f);
}

// ---------------- head: mean, dense, log_softmax ----------------
__global__ void __launch_bounds__(192) head_kernel(
    const float* __restrict__ sums, const float* __restrict__ cnt,
    const float* __restrict__ W, const float* __restrict__ bias,
    float* __restrict__ out)
{
    __shared__ float red[192][4];
    const int g = blockIdx.x;
    const int t = threadIdx.x;
    const float c = fmaxf(cnt[g], 1.f);
    float4 p = *(const float4*)(sums + (size_t)g * EMB + t * 4);
    const float inv = 1.f / c;
    p.x *= inv; p.y *= inv; p.z *= inv; p.w *= inv;
    const int f = t * 4;
#pragma unroll
    for (int o = 0; o < 4; o++) {
        red[t][o] = p.x * W[(f + 0) * 4 + o] + p.y * W[(f + 1) * 4 + o] +
                    p.z * W[(f + 2) * 4 + o] + p.w * W[(f + 3) * 4 + o];
    }
    __syncthreads();
    if (t == 0) {
        float l[4];
#pragma unroll
        for (int o = 0; o < 4; o++) {
            float s = bias[o];
            for (int i = 0; i < 192; i++) s += red[i][o];
            l[o] = s;
        }
        float m = fmaxf(fmaxf(l[0], l[1]), fmaxf(l[2], l[3]));
        float se = expf(l[0] - m) + expf(l[1] - m) + expf(l[2] - m) + expf(l[3] - m);
        float lse = m + logf(se);
#pragma unroll
        for (int o = 0; o < 4; o++) out[g * 4 + o] = l[o] - lse;
    }
}

// ---------------- launch ----------------
extern "C" void kernel_launch(void* const* d_in, const int* in_sizes, int n_in,
                              void* d_out, int out_size)
{
    const float* x       = (const float*)d_in[0];
    const int*   ei      = (const int*)d_in[1];
    const int*   batch   = (const int*)d_in[2];
    const float* conv0_w = (const float*)d_in[3];
    const float* bn0_g   = (const float*)d_in[4];
    const float* bn0_b   = (const float*)d_in[5];
    const float* bn0_m   = (const float*)d_in[6];
    const float* bn0_v   = (const float*)d_in[7];
    const float* conv1_w = (const float*)d_in[8];
    const float* conv2_w = (const float*)d_in[9];
    const float* bn2_g   = (const float*)d_in[10];
    const float* bn2_b   = (const float*)d_in[11];
    const float* bn2_m   = (const float*)d_in[12];
    const float* bn2_v   = (const float*)d_in[13];
    const float* g1w1    = (const float*)d_in[14];
    const float* g1b1    = (const float*)d_in[15];
    const float* g1w2    = (const float*)d_in[16];
    const float* g1b2    = (const float*)d_in[17];
    const float* g2w1    = (const float*)d_in[18];
    const float* g2b1    = (const float*)d_in[19];
    const float* g2w2    = (const float*)d_in[20];
    const float* g2b2    = (const float*)d_in[21];
    const float* dW      = (const float*)d_in[22];
    const float* dB      = (const float*)d_in[23];
    float* out = (float*)d_out;

    float *p_h0, *p_agg1, *p_z, *p_h1, *p_agg2, *p_h2, *p_sums, *p_cnt;
    uint32_t *p_wh, *p_wm;
    cudaGetSymbolAddress((void**)&p_h0,   g_h0);
    cudaGetSymbolAddress((void**)&p_agg1, g_agg1);
    cudaGetSymbolAddress((void**)&p_z,    g_z);
    cudaGetSymbolAddress((void**)&p_h1,   g_h1);
    cudaGetSymbolAddress((void**)&p_agg2, g_agg2);
    cudaGetSymbolAddress((void**)&p_h2,   g_h2);
    cudaGetSymbolAddress((void**)&p_sums, g_sums);
    cudaGetSymbolAddress((void**)&p_cnt,  g_cnt);
    cudaGetSymbolAddress((void**)&p_wh,   g_wh);
    cudaGetSymbolAddress((void**)&p_wm,   g_wm);

    const dim3 gemmGrid(EMB / BN, (Nn + BM - 1) / BM);

    // 0) weight prep (packed bf16 hi/mid splits)
    wprep_kernel<<<(196608 + 255) / 256, 256>>>(g1w1, p_wh + WO1, p_wm + WO1, 196608, EMB);
    wprep_kernel<<<(294912 + 255) / 256, 256>>>(g1w2, p_wh + WO2, p_wm + WO2, 294912, EMB);
    wprep_kernel<<<(294912 + 255) / 256, 256>>>(g2w1, p_wh + WO3, p_wm + WO3, 294912, EMB);
    wprep_kernel<<<(294912 + 255) / 256, 256>>>(g2w2, p_wh + WO4, p_wm + WO4, 294912, EMB);

    // 1) temporal conv stack -> h0 (N x 512)
    conv_kernel<<<Nn, 256>>>(x, conv0_w, bn0_g, bn0_b, bn0_m, bn0_v,
                             conv1_w, conv2_w, bn2_g, bn2_b, bn2_m, bn2_v, p_h0);

    // 2) GIN1 aggregation: agg1 = h0 + sum_{src->dst} h0[src]
    {
        int n4 = Nn * FIN / 4;
        copy_kernel<<<(n4 + 255) / 256, 256>>>((const float4*)p_h0, (float4*)p_agg1, n4);
        edge_agg_kernel<FIN><<<Ee, FIN / 4>>>(ei, p_h0, p_agg1);
    }
    // 3) z1 = relu(agg1@W1 + b1), h1 = relu(z1@W2 + b2)
    gemm_bf16_kernel<<<gemmGrid, 256>>>(p_agg1, p_wh + WO1, p_wm + WO1, g1b1, p_z, Nn, FIN, EMB, 1);
    gemm_bf16_kernel<<<gemmGrid, 256>>>(p_z, p_wh + WO2, p_wm + WO2, g1b2, p_h1, Nn, EMB, EMB, 1);

    // 4) GIN2 aggregation: agg2 = h1 + sum h1[src]
    {
        int n4 = Nn * EMB / 4;
        copy_kernel<<<(n4 + 255) / 256, 256>>>((const float4*)p_h1, (float4*)p_agg2, n4);
        edge_agg_kernel<EMB><<<Ee, EMB / 4>>>(ei, p_h1, p_agg2);
    }
    // 5) z2 = relu(agg2@W3 + b3), h2 = relu(z2@W4 + b4)
    gemm_bf16_kernel<<<gemmGrid, 256>>>(p_agg2, p_wh + WO3, p_wm + WO3, g2b1, p_z, Nn, EMB, EMB, 1);
    gemm_bf16_kernel<<<gemmGrid, 256>>>(p_z, p_wh + WO4, p_wm + WO4, g2b2, p_h2, Nn, EMB, EMB, 1);

    // 6) graph mean pool + dense + log_softmax
    {
        int n4s = Gg * EMB / 4;
        zero_kernel<<<(n4s + 255) / 256, 256>>>((float4*)p_sums, n4s);
        zero_kernel<<<1, 256>>>((float4*)p_cnt, Gg / 4);
        pool_kernel<<<Nn, EMB / 4>>>(batch, p_h2, p_sums, p_cnt);
        head_kernel<<<Gg, EMB / 4>>>(p_sums, p_cnt, dW, dB, out);
    }
}

// round 9
// speedup vs baseline: 2.6683x; 1.2240x over previous
#include <cuda_runtime.h>
#include <cuda_bf16.h>
#include <cuda_fp16.h>
#include <math.h>
#include <stdint.h>

#define Nn 20000
#define Tt 256
#define Ee 320000
#define Gg 64
#define CT 8
#define CP 16
#define EMB 768
#define OUTC 4
#define FIN 512
#define BN_EPS 1e-5f

// ---------------- scratch (device globals, no allocation) ----------------
__device__ float g_h0[(size_t)Nn * FIN];
__device__ float g_agg1[(size_t)Nn * FIN];
__device__ float g_z[(size_t)Nn * EMB];
__device__ float g_h1[(size_t)Nn * EMB];
__device__ float g_agg2[(size_t)Nn * EMB];
__device__ float g_h2[(size_t)Nn * EMB];
__device__ float g_sums[Gg * EMB];
__device__ float g_cnt[Gg];

// packed fp16x2 weight buffer: layout [K/2][M] uint32 (pair along k)
#define WO1 0
#define WO2 196608
#define WO3 491520
#define WO4 786432
#define WTOT 1081344
__device__ uint32_t g_wh[WTOT];

// ---------------- fused temporal conv + BN + pool ----------------
__global__ void __launch_bounds__(256) conv_kernel(
    const float* __restrict__ x,
    const float* __restrict__ w0,
    const float* __restrict__ g0, const float* __restrict__ b0,
    const float* __restrict__ m0, const float* __restrict__ v0,
    const float* __restrict__ w1,
    const float* __restrict__ w2,
    const float* __restrict__ g2, const float* __restrict__ b2,
    const float* __restrict__ m2, const float* __restrict__ v2,
    float* __restrict__ hout)
{
    __shared__ float xs[256];
    __shared__ float w0s[33 * 8];
    __shared__ float w1s[21 * 8];
    __shared__ float w2s[8 * 16];
    __shared__ float sc0[8], sh0[8], sc2[16], sh2[16];
    __shared__ float s1s[8][264];

    const int t = threadIdx.x;
    const int n = blockIdx.x;

    xs[t] = x[(size_t)n * Tt + t];
    for (int i = t; i < 33 * 8; i += 256) w0s[i] = w0[i];
    if (t < 21 * 8) w1s[t] = w1[t];
    if (t < 8 * 16) w2s[t] = w2[t];
    if (t < 8)  { float s = g0[t] * rsqrtf(v0[t] + BN_EPS); sc0[t] = s; sh0[t] = b0[t] - m0[t] * s; }
    if (t < 16) { float s = g2[t] * rsqrtf(v2[t] + BN_EPS); sc2[t] = s; sh2[t] = b2[t] - m2[t] * s; }
    __syncthreads();

    float acc[8];
#pragma unroll
    for (int c = 0; c < 8; c++) acc[c] = 0.f;
#pragma unroll
    for (int w = 0; w < 33; w++) {
        int tt = t + w - 16;
        float xv = (tt >= 0 && tt < 256) ? xs[tt] : 0.f;
#pragma unroll
        for (int c = 0; c < 8; c++) acc[c] += xv * w0s[w * 8 + c];
    }
#pragma unroll
    for (int c = 0; c < 8; c++) s1s[c][t] = acc[c] * sc0[c] + sh0[c];
    __syncthreads();

    float s2[8];
#pragma unroll
    for (int c = 0; c < 8; c++) {
        float a = 0.f;
#pragma unroll
        for (int w = 0; w < 21; w++) {
            int tt = t + w - 10;
            float xv = (tt >= 0 && tt < 256) ? s1s[c][tt] : 0.f;
            a += xv * w1s[w * 8 + c];
        }
        s2[c] = fmaxf(a, 0.f);
    }

    const int lane = t & 31;
#pragma unroll
    for (int o = 0; o < 16; o++) {
        float a = 0.f;
#pragma unroll
        for (int c = 0; c < 8; c++) a += s2[c] * w2s[c * 16 + o];
        a = fmaxf(a * sc2[o] + sh2[o], 0.f);
        a += __shfl_xor_sync(0xffffffffu, a, 1);
        a += __shfl_xor_sync(0xffffffffu, a, 2);
        a += __shfl_xor_sync(0xffffffffu, a, 4);
        if ((lane & 7) == 0)
            hout[(size_t)n * FIN + (t >> 3) * 16 + o] = a * 0.125f;
    }
}

// ---------------- utility kernels ----------------
__global__ void zero_kernel(float4* __restrict__ p, int n4)
{
    int i = blockIdx.x * blockDim.x + threadIdx.x;
    int stride = gridDim.x * blockDim.x;
    float4 z = make_float4(0.f, 0.f, 0.f, 0.f);
    for (; i < n4; i += stride) p[i] = z;
}

// copy h -> agg (initializes aggregation with self term; edges add on top)
__global__ void copy_kernel(const float4* __restrict__ src, float4* __restrict__ dst, int n4)
{
    int i = blockIdx.x * blockDim.x + threadIdx.x;
    int stride = gridDim.x * blockDim.x;
    for (; i < n4; i += stride) dst[i] = src[i];
}

// ---------------- weight prep: fp32 [K][M] -> packed fp16x2 [K/2][M] ----
__global__ void __launch_bounds__(256) wprep_kernel(
    const float* __restrict__ W, uint32_t* __restrict__ Wh, int total, int M)
{
    int idx = blockIdx.x * blockDim.x + threadIdx.x;
    if (idx >= total) return;
    int kp = idx / M, n = idx - kp * M;
    float f0 = W[(size_t)(2 * kp) * M + n];
    float f1 = W[(size_t)(2 * kp + 1) * M + n];
    __half2 h = __floats2half2_rn(f0, f1);
    Wh[idx] = *(uint32_t*)&h;
}

// ---------------- edge aggregation: agg[dst] += h[src] (red.v4) ----------------
template <int F>
__global__ void __launch_bounds__(F / 4) edge_agg_kernel(
    const int* __restrict__ ei, const float* __restrict__ h, float* __restrict__ agg)
{
    const int e = blockIdx.x;
    const int src = __ldg(ei + e);
    const int dst = __ldg(ei + Ee + e);
    const int f = threadIdx.x;
    float4 v = __ldg((const float4*)(h + (size_t)src * F) + f);
    float* a = agg + (size_t)dst * F + f * 4;
    asm volatile("red.global.add.v4.f32 [%0], {%1,%2,%3,%4};"
                 :: "l"(a), "f"(v.x), "f"(v.y), "f"(v.z), "f"(v.w) : "memory");
}

// ---------------- fp16 2-pass tensor-core GEMM --------------------------------
// C = act(A @ B + bias); A: Nrows x K fp32 row-major, split in-kernel to fp16 hi+mid.
// B pre-rounded to fp16, packed pairs [K/2][M] uint32.
// D += Ah*B + Am*B  (B single-rounded: error ~2^-12, well under 1e-3 threshold)
// Block tile 128x128, BK=32, 256 threads, warps 4(m) x 2(n), warp tile 32x64.
#define BM 128
#define BN 128
#define BK 32
#define KP 16          // pairs per k-tile
#define AS_STRIDE 20   // KP + 4
#define BS_STRIDE 136  // BN + 8

__device__ __forceinline__ void mma_fp16(
    float* d, const uint32_t* a, uint32_t b0, uint32_t b1)
{
    asm volatile(
        "mma.sync.aligned.m16n8k16.row.col.f32.f16.f16.f32 "
        "{%0,%1,%2,%3}, {%4,%5,%6,%7}, {%8,%9}, {%0,%1,%2,%3};"
        : "+f"(d[0]), "+f"(d[1]), "+f"(d[2]), "+f"(d[3])
        : "r"(a[0]), "r"(a[1]), "r"(a[2]), "r"(a[3]), "r"(b0), "r"(b1));
}

__global__ void __launch_bounds__(256, 2) gemm_fp16_kernel(
    const float* __restrict__ A,
    const uint32_t* __restrict__ Bh,
    const float* __restrict__ bias,
    float* __restrict__ C, int Nrows, int K, int M, int doRelu)
{
    __shared__ uint32_t As_h[BM][AS_STRIDE];
    __shared__ uint32_t As_m[BM][AS_STRIDE];
    __shared__ uint32_t Bs_h[KP][BS_STRIDE];

    const int tid = threadIdx.x;
    const int lane = tid & 31;
    const int warp = tid >> 5;
    const int warp_m = warp & 3;
    const int warp_n = warp >> 2;
    const int rowBase = blockIdx.y * BM;
    const int colBase = blockIdx.x * BN;

    const int r0 = tid >> 2;      // 0..63 (rows r0, r0+64)
    const int c4 = tid & 3;       // 0..3 (k-floats c4*8..+7)
    const int kp0 = tid >> 5;     // 0..7 (kpairs kp0, kp0+8)
    const int n4 = tid & 31;      // 0..31 (n = n4*4..+3)

    float acc[2][8][4];
#pragma unroll
    for (int i = 0; i < 2; i++)
#pragma unroll
        for (int j = 0; j < 8; j++)
#pragma unroll
            for (int r = 0; r < 4; r++) acc[i][j][r] = 0.f;

    float aF[2][8];
    uint4 bHreg[2];

    // ---- prefetch k0 = 0 ----
    {
#pragma unroll
        for (int h = 0; h < 2; h++) {
            int r = rowBase + r0 + h * 64;
            if (r < Nrows) {
                float4 u = *(const float4*)(A + (size_t)r * K + c4 * 8);
                float4 v = *(const float4*)(A + (size_t)r * K + c4 * 8 + 4);
                aF[h][0] = u.x; aF[h][1] = u.y; aF[h][2] = u.z; aF[h][3] = u.w;
                aF[h][4] = v.x; aF[h][5] = v.y; aF[h][6] = v.z; aF[h][7] = v.w;
            } else {
#pragma unroll
                for (int q = 0; q < 8; q++) aF[h][q] = 0.f;
            }
        }
#pragma unroll
        for (int h = 0; h < 2; h++) {
            size_t off = (size_t)(kp0 + h * 8) * M + colBase + n4 * 4;
            bHreg[h] = *(const uint4*)(Bh + off);
        }
    }

    for (int k0 = 0; k0 < K; k0 += BK) {
        // ---- convert + store staged data to smem ----
#pragma unroll
        for (int h = 0; h < 2; h++) {
            int row = r0 + h * 64;
            uint32_t hi[4], mi[4];
#pragma unroll
            for (int p = 0; p < 4; p++) {
                float f0 = aF[h][2 * p], f1 = aF[h][2 * p + 1];
                __half2 bh = __floats2half2_rn(f0, f1);
                float rr0 = f0 - __half2float(__low2half(bh));
                float rr1 = f1 - __half2float(__high2half(bh));
                __half2 bm = __floats2half2_rn(rr0, rr1);
                hi[p] = *(uint32_t*)&bh;
                mi[p] = *(uint32_t*)&bm;
            }
            *(uint4*)&As_h[row][c4 * 4] = make_uint4(hi[0], hi[1], hi[2], hi[3]);
            *(uint4*)&As_m[row][c4 * 4] = make_uint4(mi[0], mi[1], mi[2], mi[3]);
        }
#pragma unroll
        for (int h = 0; h < 2; h++) {
            *(uint4*)&Bs_h[kp0 + h * 8][n4 * 4] = bHreg[h];
        }
        __syncthreads();

        // ---- prefetch next ----
        if (k0 + BK < K) {
            const int kn = k0 + BK;
#pragma unroll
            for (int h = 0; h < 2; h++) {
                int r = rowBase + r0 + h * 64;
                if (r < Nrows) {
                    float4 u = *(const float4*)(A + (size_t)r * K + kn + c4 * 8);
                    float4 v = *(const float4*)(A + (size_t)r * K + kn + c4 * 8 + 4);
                    aF[h][0] = u.x; aF[h][1] = u.y; aF[h][2] = u.z; aF[h][3] = u.w;
                    aF[h][4] = v.x; aF[h][5] = v.y; aF[h][6] = v.z; aF[h][7] = v.w;
                } else {
#pragma unroll
                    for (int q = 0; q < 8; q++) aF[h][q] = 0.f;
                }
            }
#pragma unroll
            for (int h = 0; h < 2; h++) {
                size_t off = (size_t)(kn / 2 + kp0 + h * 8) * M + colBase + n4 * 4;
                bHreg[h] = *(const uint4*)(Bh + off);
            }
        }

        // ---- compute: 2 k16 steps, 2 MMA passes (Ah*B + Am*B) ----
#pragma unroll
        for (int step = 0; step < 2; step++) {
            const int koff = step * 8;
            uint32_t ah[2][4], am[2][4];
#pragma unroll
            for (int i = 0; i < 2; i++) {
                int mr = warp_m * 32 + i * 16 + (lane >> 2);
                int kc = koff + (lane & 3);
                ah[i][0] = As_h[mr][kc];
                ah[i][1] = As_h[mr + 8][kc];
                ah[i][2] = As_h[mr][kc + 4];
                ah[i][3] = As_h[mr + 8][kc + 4];
                am[i][0] = As_m[mr][kc];
                am[i][1] = As_m[mr + 8][kc];
                am[i][2] = As_m[mr][kc + 4];
                am[i][3] = As_m[mr + 8][kc + 4];
            }
#pragma unroll
            for (int j = 0; j < 8; j++) {
                int kb = koff + (lane & 3);
                int nb = warp_n * 64 + j * 8 + (lane >> 2);
                uint32_t bh0 = Bs_h[kb][nb];
                uint32_t bh1 = Bs_h[kb + 4][nb];
#pragma unroll
                for (int i = 0; i < 2; i++) {
                    mma_fp16(acc[i][j], ah[i], bh0, bh1);
                    mma_fp16(acc[i][j], am[i], bh0, bh1);
                }
            }
        }
        __syncthreads();
    }

    // ---- epilogue ----
#pragma unroll
    for (int i = 0; i < 2; i++) {
        int r = rowBase + warp_m * 32 + i * 16 + (lane >> 2);
#pragma unroll
        for (int j = 0; j < 8; j++) {
            int c0 = colBase + warp_n * 64 + j * 8 + (lane & 3) * 2;
            float b0v = bias[c0];
            float b1v = bias[c0 + 1];
            float v0 = acc[i][j][0] + b0v;
            float v1 = acc[i][j][1] + b1v;
            float v2 = acc[i][j][2] + b0v;
            float v3 = acc[i][j][3] + b1v;
            if (doRelu) {
                v0 = fmaxf(v0, 0.f); v1 = fmaxf(v1, 0.f);
                v2 = fmaxf(v2, 0.f); v3 = fmaxf(v3, 0.f);
            }
            if (r < Nrows) {
                C[(size_t)r * M + c0] = v0;
                C[(size_t)r * M + c0 + 1] = v1;
            }
            if (r + 8 < Nrows) {
                C[(size_t)(r + 8) * M + c0] = v2;
                C[(size_t)(r + 8) * M + c0 + 1] = v3;
            }
        }
    }
}

// ---------------- graph mean-pool: sums/counts (red.v4) ----------------
__global__ void __launch_bounds__(192) pool_kernel(
    const int* __restrict__ batch, const float* __restrict__ h,
    float* __restrict__ sums, float* __restrict__ cnt)
{
    const int n = blockIdx.x;
    const int b = __ldg(batch + n);
    const int f = threadIdx.x;
    float4 v = __ldg((const float4*)(h + (size_t)n * EMB) + f);
    float* s = sums + (size_t)b * EMB + f * 4;
    asm volatile("red.global.add.v4.f32 [%0], {%1,%2,%3,%4};"
                 :: "l"(s), "f"(v.x), "f"(v.y), "f"(v.z), "f"(v.w) : "memory");
    if (f == 0) atomicAdd(&cnt[b], 1.0f);
}

// ---------------- head: mean, dense, log_softmax ----------------
__global__ void __launch_bounds__(192) head_kernel(
    const float* __restrict__ sums, const float* __restrict__ cnt,
    const float* __restrict__ W, const float* __restrict__ bias,
    float* __restrict__ out)
{
    __shared__ float red[192][4];
    const int g = blockIdx.x;
    const int t = threadIdx.x;
    const float c = fmaxf(cnt[g], 1.f);
    float4 p = *(const float4*)(sums + (size_t)g * EMB + t * 4);
    const float inv = 1.f / c;
    p.x *= inv; p.y *= inv; p.z *= inv; p.w *= inv;
    const int f = t * 4;
#pragma unroll
    for (int o = 0; o < 4; o++) {
        red[t][o] = p.x * W[(f + 0) * 4 + o] + p.y * W[(f + 1) * 4 + o] +
                    p.z * W[(f + 2) * 4 + o] + p.w * W[(f + 3) * 4 + o];
    }
    __syncthreads();
    if (t == 0) {
        float l[4];
#pragma unroll
        for (int o = 0; o < 4; o++) {
            float s = bias[o];
            for (int i = 0; i < 192; i++) s += red[i][o];
            l[o] = s;
        }
        float m = fmaxf(fmaxf(l[0], l[1]), fmaxf(l[2], l[3]));
        float se = expf(l[0] - m) + expf(l[1] - m) + expf(l[2] - m) + expf(l[3] - m);
        float lse = m + logf(se);
#pragma unroll
        for (int o = 0; o < 4; o++) out[g * 4 + o] = l[o] - lse;
    }
}

// ---------------- launch ----------------
extern "C" void kernel_launch(void* const* d_in, const int* in_sizes, int n_in,
                              void* d_out, int out_size)
{
    const float* x       = (const float*)d_in[0];
    const int*   ei      = (const int*)d_in[1];
    const int*   batch   = (const int*)d_in[2];
    const float* conv0_w = (const float*)d_in[3];
    const float* bn0_g   = (const float*)d_in[4];
    const float* bn0_b   = (const float*)d_in[5];
    const float* bn0_m   = (const float*)d_in[6];
    const float* bn0_v   = (const float*)d_in[7];
    const float* conv1_w = (const float*)d_in[8];
    const float* conv2_w = (const float*)d_in[9];
    const float* bn2_g   = (const float*)d_in[10];
    const float* bn2_b   = (const float*)d_in[11];
    const float* bn2_m   = (const float*)d_in[12];
    const float* bn2_v   = (const float*)d_in[13];
    const float* g1w1    = (const float*)d_in[14];
    const float* g1b1    = (const float*)d_in[15];
    const float* g1w2    = (const float*)d_in[16];
    const float* g1b2    = (const float*)d_in[17];
    const float* g2w1    = (const float*)d_in[18];
    const float* g2b1    = (const float*)d_in[19];
    const float* g2w2    = (const float*)d_in[20];
    const float* g2b2    = (const float*)d_in[21];
    const float* dW      = (const float*)d_in[22];
    const float* dB      = (const float*)d_in[23];
    float* out = (float*)d_out;

    float *p_h0, *p_agg1, *p_z, *p_h1, *p_agg2, *p_h2, *p_sums, *p_cnt;
    uint32_t *p_wh;
    cudaGetSymbolAddress((void**)&p_h0,   g_h0);
    cudaGetSymbolAddress((void**)&p_agg1, g_agg1);
    cudaGetSymbolAddress((void**)&p_z,    g_z);
    cudaGetSymbolAddress((void**)&p_h1,   g_h1);
    cudaGetSymbolAddress((void**)&p_agg2, g_agg2);
    cudaGetSymbolAddress((void**)&p_h2,   g_h2);
    cudaGetSymbolAddress((void**)&p_sums, g_sums);
    cudaGetSymbolAddress((void**)&p_cnt,  g_cnt);
    cudaGetSymbolAddress((void**)&p_wh,   g_wh);

    const dim3 gemmGrid(EMB / BN, (Nn + BM - 1) / BM);

    // 0) weight prep (packed fp16 pairs)
    wprep_kernel<<<(196608 + 255) / 256, 256>>>(g1w1, p_wh + WO1, 196608, EMB);
    wprep_kernel<<<(294912 + 255) / 256, 256>>>(g1w2, p_wh + WO2, 294912, EMB);
    wprep_kernel<<<(294912 + 255) / 256, 256>>>(g2w1, p_wh + WO3, 294912, EMB);
    wprep_kernel<<<(294912 + 255) / 256, 256>>>(g2w2, p_wh + WO4, 294912, EMB);

    // 1) temporal conv stack -> h0 (N x 512)
    conv_kernel<<<Nn, 256>>>(x, conv0_w, bn0_g, bn0_b, bn0_m, bn0_v,
                             conv1_w, conv2_w, bn2_g, bn2_b, bn2_m, bn2_v, p_h0);

    // 2) GIN1 aggregation: agg1 = h0 + sum_{src->dst} h0[src]
    {
        int n4 = Nn * FIN / 4;
        copy_kernel<<<(n4 + 255) / 256, 256>>>((const float4*)p_h0, (float4*)p_agg1, n4);
        edge_agg_kernel<FIN><<<Ee, FIN / 4>>>(ei, p_h0, p_agg1);
    }
    // 3) z1 = relu(agg1@W1 + b1), h1 = relu(z1@W2 + b2)
    gemm_fp16_kernel<<<gemmGrid, 256>>>(p_agg1, p_wh + WO1, g1b1, p_z, Nn, FIN, EMB, 1);
    gemm_fp16_kernel<<<gemmGrid, 256>>>(p_z, p_wh + WO2, g1b2, p_h1, Nn, EMB, EMB, 1);

    // 4) GIN2 aggregation: agg2 = h1 + sum h1[src]
    {
        int n4 = Nn * EMB / 4;
        copy_kernel<<<(n4 + 255) / 256, 256>>>((const float4*)p_h1, (float4*)p_agg2, n4);
        edge_agg_kernel<EMB><<<Ee, EMB / 4>>>(ei, p_h1, p_agg2);
    }
    // 5) z2 = relu(agg2@W3 + b3), h2 = relu(z2@W4 + b4)
    gemm_fp16_kernel<<<gemmGrid, 256>>>(p_agg2, p_wh + WO3, g2b1, p_z, Nn, EMB, EMB, 1);
    gemm_fp16_kernel<<<gemmGrid, 256>>>(p_z, p_wh + WO4, g2b2, p_h2, Nn, EMB, EMB, 1);

    // 6) graph mean pool + dense + log_softmax
    {
        int n4s = Gg * EMB / 4;
        zero_kernel<<<(n4s + 255) / 256, 256>>>((float4*)p_sums, n4s);
        zero_kernel<<<1, 256>>>((float4*)p_cnt, Gg / 4);
        pool_kernel<<<Nn, EMB / 4>>>(batch, p_h2, p_sums, p_cnt);
        head_kernel<<<Gg, EMB / 4>>>(p_sums, p_cnt, dW, dB, out);
    }
}

// round 10
// speedup vs baseline: 3.3217x; 1.2449x over previous
#include <cuda_runtime.h>
#include <cuda_bf16.h>
#include <cuda_fp16.h>
#include <math.h>
#include <stdint.h>

#define Nn 20000
#define Tt 256
#define Ee 320000
#define Gg 64
#define CT 8
#define CP 16
#define EMB 768
#define OUTC 4
#define FIN 512
#define BN_EPS 1e-5f

// ---------------- scratch (device globals, no allocation) ----------------
__device__ float g_h0[(size_t)Nn * FIN];
__device__ float g_agg1[(size_t)Nn * FIN];
__device__ float g_z[(size_t)Nn * EMB];
__device__ float g_h1[(size_t)Nn * EMB];
__device__ float g_agg2[(size_t)Nn * EMB];
__device__ float g_h2[(size_t)Nn * EMB];
__device__ float g_sums[Gg * EMB];
__device__ float g_cnt[Gg];

// CSR scratch (built per launch; edges identical for both GIN layers)
__device__ int g_deg[Nn];
__device__ int g_off[Nn + 4];
__device__ int g_pos[Nn];
__device__ int g_elist[Ee];

// packed fp16x2 weight buffer: layout [K/2][M] uint32 (pair along k)
#define WO1 0
#define WO2 196608
#define WO3 491520
#define WO4 786432
#define WTOT 1081344
__device__ uint32_t g_wh[WTOT];

// ---------------- fused temporal conv + BN + pool ----------------
__global__ void __launch_bounds__(256) conv_kernel(
    const float* __restrict__ x,
    const float* __restrict__ w0,
    const float* __restrict__ g0, const float* __restrict__ b0,
    const float* __restrict__ m0, const float* __restrict__ v0,
    const float* __restrict__ w1,
    const float* __restrict__ w2,
    const float* __restrict__ g2, const float* __restrict__ b2,
    const float* __restrict__ m2, const float* __restrict__ v2,
    float* __restrict__ hout)
{
    __shared__ float xs[256];
    __shared__ float w0s[33 * 8];
    __shared__ float w1s[21 * 8];
    __shared__ float w2s[8 * 16];
    __shared__ float sc0[8], sh0[8], sc2[16], sh2[16];
    __shared__ float s1s[8][264];

    const int t = threadIdx.x;
    const int n = blockIdx.x;

    xs[t] = x[(size_t)n * Tt + t];
    for (int i = t; i < 33 * 8; i += 256) w0s[i] = w0[i];
    if (t < 21 * 8) w1s[t] = w1[t];
    if (t < 8 * 16) w2s[t] = w2[t];
    if (t < 8)  { float s = g0[t] * rsqrtf(v0[t] + BN_EPS); sc0[t] = s; sh0[t] = b0[t] - m0[t] * s; }
    if (t < 16) { float s = g2[t] * rsqrtf(v2[t] + BN_EPS); sc2[t] = s; sh2[t] = b2[t] - m2[t] * s; }
    __syncthreads();

    float acc[8];
#pragma unroll
    for (int c = 0; c < 8; c++) acc[c] = 0.f;
#pragma unroll
    for (int w = 0; w < 33; w++) {
        int tt = t + w - 16;
        float xv = (tt >= 0 && tt < 256) ? xs[tt] : 0.f;
#pragma unroll
        for (int c = 0; c < 8; c++) acc[c] += xv * w0s[w * 8 + c];
    }
#pragma unroll
    for (int c = 0; c < 8; c++) s1s[c][t] = acc[c] * sc0[c] + sh0[c];
    __syncthreads();

    float s2[8];
#pragma unroll
    for (int c = 0; c < 8; c++) {
        float a = 0.f;
#pragma unroll
        for (int w = 0; w < 21; w++) {
            int tt = t + w - 10;
            float xv = (tt >= 0 && tt < 256) ? s1s[c][tt] : 0.f;
            a += xv * w1s[w * 8 + c];
        }
        s2[c] = fmaxf(a, 0.f);
    }

    const int lane = t & 31;
#pragma unroll
    for (int o = 0; o < 16; o++) {
        float a = 0.f;
#pragma unroll
        for (int c = 0; c < 8; c++) a += s2[c] * w2s[c * 16 + o];
        a = fmaxf(a * sc2[o] + sh2[o], 0.f);
        a += __shfl_xor_sync(0xffffffffu, a, 1);
        a += __shfl_xor_sync(0xffffffffu, a, 2);
        a += __shfl_xor_sync(0xffffffffu, a, 4);
        if ((lane & 7) == 0)
            hout[(size_t)n * FIN + (t >> 3) * 16 + o] = a * 0.125f;
    }
}

// ---------------- utility kernels ----------------
__global__ void zero_kernel(float4* __restrict__ p, int n4)
{
    int i = blockIdx.x * blockDim.x + threadIdx.x;
    int stride = gridDim.x * blockDim.x;
    float4 z = make_float4(0.f, 0.f, 0.f, 0.f);
    for (; i < n4; i += stride) p[i] = z;
}

// ---------------- weight prep: fp32 [K][M] -> packed fp16x2 [K/2][M] ----
__global__ void __launch_bounds__(256) wprep_kernel(
    const float* __restrict__ W, uint32_t* __restrict__ Wh, int total, int M)
{
    int idx = blockIdx.x * blockDim.x + threadIdx.x;
    if (idx >= total) return;
    int kp = idx / M, n = idx - kp * M;
    float f0 = W[(size_t)(2 * kp) * M + n];
    float f1 = W[(size_t)(2 * kp + 1) * M + n];
    __half2 h = __floats2half2_rn(f0, f1);
    Wh[idx] = *(uint32_t*)&h;
}

// ---------------- CSR build ----------------
__global__ void count_kernel(const int* __restrict__ ei, int* __restrict__ deg)
{
    int e = blockIdx.x * blockDim.x + threadIdx.x;
    if (e < Ee) atomicAdd(&deg[__ldg(ei + Ee + e)], 1);
}

// single-block hierarchical exclusive scan of deg[0..n) -> off, pos; off[n]=total
__global__ void __launch_bounds__(1024) scan_kernel(
    const int* __restrict__ deg, int* __restrict__ off, int* __restrict__ pos, int n)
{
    __shared__ int wsum[32];
    __shared__ int sbase;
    const int tid = threadIdx.x, lane = tid & 31, wid = tid >> 5;
    if (tid == 0) sbase = 0;
    __syncthreads();
    for (int start = 0; start < n; start += 1024) {
        int idx = start + tid;
        int v = (idx < n) ? deg[idx] : 0;
        int x = v;
#pragma unroll
        for (int d = 1; d < 32; d <<= 1) {
            int y = __shfl_up_sync(0xffffffffu, x, d);
            if (lane >= d) x += y;
        }
        if (lane == 31) wsum[wid] = x;
        __syncthreads();
        if (wid == 0) {
            int w = wsum[lane];
#pragma unroll
            for (int d = 1; d < 32; d <<= 1) {
                int y = __shfl_up_sync(0xffffffffu, w, d);
                if (lane >= d) w += y;
            }
            wsum[lane] = w;
        }
        __syncthreads();
        int warpoff = (wid == 0) ? 0 : wsum[wid - 1];
        int excl = sbase + warpoff + x - v;
        if (idx < n) { off[idx] = excl; pos[idx] = excl; }
        int total = wsum[31];
        __syncthreads();
        if (tid == 0) sbase += total;
        __syncthreads();
    }
    if (tid == 0) off[n] = sbase;
}

__global__ void fill_kernel(const int* __restrict__ ei,
                            int* __restrict__ pos, int* __restrict__ elist)
{
    int e = blockIdx.x * blockDim.x + threadIdx.x;
    if (e < Ee) {
        int d = __ldg(ei + Ee + e);
        int p = atomicAdd(&pos[d], 1);
        elist[p] = __ldg(ei + e);
    }
}

// ---------------- CSR gather: agg[n] = h[n] + sum_{src in in(n)} h[src] ------
template <int F>
__global__ void __launch_bounds__(F / 4) gather_kernel(
    const int* __restrict__ off, const int* __restrict__ elist,
    const float* __restrict__ h, float* __restrict__ agg)
{
    const int n = blockIdx.x;
    const int f = threadIdx.x;  // F/4 threads, one float4 each
    float4 acc = __ldg((const float4*)(h + (size_t)n * F) + f);
    int s = __ldg(off + n);
    const int e = __ldg(off + n + 1);
    // 2-way unroll for memory-level parallelism (rows are L2-resident)
    for (; s + 1 < e; s += 2) {
        int s0 = __ldg(elist + s);
        int s1 = __ldg(elist + s + 1);
        float4 v0 = __ldg((const float4*)(h + (size_t)s0 * F) + f);
        float4 v1 = __ldg((const float4*)(h + (size_t)s1 * F) + f);
        acc.x += v0.x + v1.x;
        acc.y += v0.y + v1.y;
        acc.z += v0.z + v1.z;
        acc.w += v0.w + v1.w;
    }
    if (s < e) {
        int s0 = __ldg(elist + s);
        float4 v0 = __ldg((const float4*)(h + (size_t)s0 * F) + f);
        acc.x += v0.x; acc.y += v0.y; acc.z += v0.z; acc.w += v0.w;
    }
    *((float4*)(agg + (size_t)n * F) + f) = acc;
}

// ---------------- fp16 2-pass tensor-core GEMM --------------------------------
#define BM 128
#define BN 128
#define BK 32
#define KP 16
#define AS_STRIDE 20
#define BS_STRIDE 136

__device__ __forceinline__ void mma_fp16(
    float* d, const uint32_t* a, uint32_t b0, uint32_t b1)
{
    asm volatile(
        "mma.sync.aligned.m16n8k16.row.col.f32.f16.f16.f32 "
        "{%0,%1,%2,%3}, {%4,%5,%6,%7}, {%8,%9}, {%0,%1,%2,%3};"
        : "+f"(d[0]), "+f"(d[1]), "+f"(d[2]), "+f"(d[3])
        : "r"(a[0]), "r"(a[1]), "r"(a[2]), "r"(a[3]), "r"(b0), "r"(b1));
}

__global__ void __launch_bounds__(256, 2) gemm_fp16_kernel(
    const float* __restrict__ A,
    const uint32_t* __restrict__ Bh,
    const float* __restrict__ bias,
    float* __restrict__ C, int Nrows, int K, int M, int doRelu)
{
    __shared__ uint32_t As_h[BM][AS_STRIDE];
    __shared__ uint32_t As_m[BM][AS_STRIDE];
    __shared__ uint32_t Bs_h[KP][BS_STRIDE];

    const int tid = threadIdx.x;
    const int lane = tid & 31;
    const int warp = tid >> 5;
    const int warp_m = warp & 3;
    const int warp_n = warp >> 2;
    const int rowBase = blockIdx.y * BM;
    const int colBase = blockIdx.x * BN;

    const int r0 = tid >> 2;
    const int c4 = tid & 3;
    const int kp0 = tid >> 5;
    const int n4 = tid & 31;

    float acc[2][8][4];
#pragma unroll
    for (int i = 0; i < 2; i++)
#pragma unroll
        for (int j = 0; j < 8; j++)
#pragma unroll
            for (int r = 0; r < 4; r++) acc[i][j][r] = 0.f;

    float aF[2][8];
    uint4 bHreg[2];

    {
#pragma unroll
        for (int h = 0; h < 2; h++) {
            int r = rowBase + r0 + h * 64;
            if (r < Nrows) {
                float4 u = *(const float4*)(A + (size_t)r * K + c4 * 8);
                float4 v = *(const float4*)(A + (size_t)r * K + c4 * 8 + 4);
                aF[h][0] = u.x; aF[h][1] = u.y; aF[h][2] = u.z; aF[h][3] = u.w;
                aF[h][4] = v.x; aF[h][5] = v.y; aF[h][6] = v.z; aF[h][7] = v.w;
            } else {
#pragma unroll
                for (int q = 0; q < 8; q++) aF[h][q] = 0.f;
            }
        }
#pragma unroll
        for (int h = 0; h < 2; h++) {
            size_t off = (size_t)(kp0 + h * 8) * M + colBase + n4 * 4;
            bHreg[h] = *(const uint4*)(Bh + off);
        }
    }

    for (int k0 = 0; k0 < K; k0 += BK) {
#pragma unroll
        for (int h = 0; h < 2; h++) {
            int row = r0 + h * 64;
            uint32_t hi[4], mi[4];
#pragma unroll
            for (int p = 0; p < 4; p++) {
                float f0 = aF[h][2 * p], f1 = aF[h][2 * p + 1];
                __half2 bh = __floats2half2_rn(f0, f1);
                float rr0 = f0 - __half2float(__low2half(bh));
                float rr1 = f1 - __half2float(__high2half(bh));
                __half2 bm = __floats2half2_rn(rr0, rr1);
                hi[p] = *(uint32_t*)&bh;
                mi[p] = *(uint32_t*)&bm;
            }
            *(uint4*)&As_h[row][c4 * 4] = make_uint4(hi[0], hi[1], hi[2], hi[3]);
            *(uint4*)&As_m[row][c4 * 4] = make_uint4(mi[0], mi[1], mi[2], mi[3]);
        }
#pragma unroll
        for (int h = 0; h < 2; h++) {
            *(uint4*)&Bs_h[kp0 + h * 8][n4 * 4] = bHreg[h];
        }
        __syncthreads();

        if (k0 + BK < K) {
            const int kn = k0 + BK;
#pragma unroll
            for (int h = 0; h < 2; h++) {
                int r = rowBase + r0 + h * 64;
                if (r < Nrows) {
                    float4 u = *(const float4*)(A + (size_t)r * K + kn + c4 * 8);
                    float4 v = *(const float4*)(A + (size_t)r * K + kn + c4 * 8 + 4);
                    aF[h][0] = u.x; aF[h][1] = u.y; aF[h][2] = u.z; aF[h][3] = u.w;
                    aF[h][4] = v.x; aF[h][5] = v.y; aF[h][6] = v.z; aF[h][7] = v.w;
                } else {
#pragma unroll
                    for (int q = 0; q < 8; q++) aF[h][q] = 0.f;
                }
            }
#pragma unroll
            for (int h = 0; h < 2; h++) {
                size_t off = (size_t)(kn / 2 + kp0 + h * 8) * M + colBase + n4 * 4;
                bHreg[h] = *(const uint4*)(Bh + off);
            }
        }

#pragma unroll
        for (int step = 0; step < 2; step++) {
            const int koff = step * 8;
            uint32_t ah[2][4], am[2][4];
#pragma unroll
            for (int i = 0; i < 2; i++) {
                int mr = warp_m * 32 + i * 16 + (lane >> 2);
                int kc = koff + (lane & 3);
                ah[i][0] = As_h[mr][kc];
                ah[i][1] = As_h[mr + 8][kc];
                ah[i][2] = As_h[mr][kc + 4];
                ah[i][3] = As_h[mr + 8][kc + 4];
                am[i][0] = As_m[mr][kc];
                am[i][1] = As_m[mr + 8][kc];
                am[i][2] = As_m[mr][kc + 4];
                am[i][3] = As_m[mr + 8][kc + 4];
            }
#pragma unroll
            for (int j = 0; j < 8; j++) {
                int kb = koff + (lane & 3);
                int nb = warp_n * 64 + j * 8 + (lane >> 2);
                uint32_t bh0 = Bs_h[kb][nb];
                uint32_t bh1 = Bs_h[kb + 4][nb];
#pragma unroll
                for (int i = 0; i < 2; i++) {
                    mma_fp16(acc[i][j], ah[i], bh0, bh1);
                    mma_fp16(acc[i][j], am[i], bh0, bh1);
                }
            }
        }
        __syncthreads();
    }

#pragma unroll
    for (int i = 0; i < 2; i++) {
        int r = rowBase + warp_m * 32 + i * 16 + (lane >> 2);
#pragma unroll
        for (int j = 0; j < 8; j++) {
            int c0 = colBase + warp_n * 64 + j * 8 + (lane & 3) * 2;
            float b0v = bias[c0];
            float b1v = bias[c0 + 1];
            float v0 = acc[i][j][0] + b0v;
            float v1 = acc[i][j][1] + b1v;
            float v2 = acc[i][j][2] + b0v;
            float v3 = acc[i][j][3] + b1v;
            if (doRelu) {
                v0 = fmaxf(v0, 0.f); v1 = fmaxf(v1, 0.f);
                v2 = fmaxf(v2, 0.f); v3 = fmaxf(v3, 0.f);
            }
            if (r < Nrows) {
                C[(size_t)r * M + c0] = v0;
                C[(size_t)r * M + c0 + 1] = v1;
            }
            if (r + 8 < Nrows) {
                C[(size_t)(r + 8) * M + c0] = v2;
                C[(size_t)(r + 8) * M + c0 + 1] = v3;
            }
        }
    }
}

// ---------------- graph mean-pool: sums/counts (red.v4) ----------------
__global__ void __launch_bounds__(192) pool_kernel(
    const int* __restrict__ batch, const float* __restrict__ h,
    float* __restrict__ sums, float* __restrict__ cnt)
{
    const int n = blockIdx.x;
    const int b = __ldg(batch + n);
    const int f = threadIdx.x;
    float4 v = __ldg((const float4*)(h + (size_t)n * EMB) + f);
    float* s = sums + (size_t)b * EMB + f * 4;
    asm volatile("red.global.add.v4.f32 [%0], {%1,%2,%3,%4};"
                 :: "l"(s), "f"(v.x), "f"(v.y), "f"(v.z), "f"(v.w) : "memory");
    if (f == 0) atomicAdd(&cnt[b], 1.0f);
}

// ---------------- head: mean, dense, log_softmax ----------------
__global__ void __launch_bounds__(192) head_kernel(
    const float* __restrict__ sums, const float* __restrict__ cnt,
    const float* __restrict__ W, const float* __restrict__ bias,
    float* __restrict__ out)
{
    __shared__ float red[192][4];
    const int g = blockIdx.x;
    const int t = threadIdx.x;
    const float c = fmaxf(cnt[g], 1.f);
    float4 p = *(const float4*)(sums + (size_t)g * EMB + t * 4);
    const float inv = 1.f / c;
    p.x *= inv; p.y *= inv; p.z *= inv; p.w *= inv;
    const int f = t * 4;
#pragma unroll
    for (int o = 0; o < 4; o++) {
        red[t][o] = p.x * W[(f + 0) * 4 + o] + p.y * W[(f + 1) * 4 + o] +
                    p.z * W[(f + 2) * 4 + o] + p.w * W[(f + 3) * 4 + o];
    }
    __syncthreads();
    if (t == 0) {
        float l[4];
#pragma unroll
        for (int o = 0; o < 4; o++) {
            float s = bias[o];
            for (int i = 0; i < 192; i++) s += red[i][o];
            l[o] = s;
        }
        float m = fmaxf(fmaxf(l[0], l[1]), fmaxf(l[2], l[3]));
        float se = expf(l[0] - m) + expf(l[1] - m) + expf(l[2] - m) + expf(l[3] - m);
        float lse = m + logf(se);
#pragma unroll
        for (int o = 0; o < 4; o++) out[g * 4 + o] = l[o] - lse;
    }
}

// ---------------- launch ----------------
extern "C" void kernel_launch(void* const* d_in, const int* in_sizes, int n_in,
                              void* d_out, int out_size)
{
    const float* x       = (const float*)d_in[0];
    const int*   ei      = (const int*)d_in[1];
    const int*   batch   = (const int*)d_in[2];
    const float* conv0_w = (const float*)d_in[3];
    const float* bn0_g   = (const float*)d_in[4];
    const float* bn0_b   = (const float*)d_in[5];
    const float* bn0_m   = (const float*)d_in[6];
    const float* bn0_v   = (const float*)d_in[7];
    const float* conv1_w = (const float*)d_in[8];
    const float* conv2_w = (const float*)d_in[9];
    const float* bn2_g   = (const float*)d_in[10];
    const float* bn2_b   = (const float*)d_in[11];
    const float* bn2_m   = (const float*)d_in[12];
    const float* bn2_v   = (const float*)d_in[13];
    const float* g1w1    = (const float*)d_in[14];
    const float* g1b1    = (const float*)d_in[15];
    const float* g1w2    = (const float*)d_in[16];
    const float* g1b2    = (const float*)d_in[17];
    const float* g2w1    = (const float*)d_in[18];
    const float* g2b1    = (const float*)d_in[19];
    const float* g2w2    = (const float*)d_in[20];
    const float* g2b2    = (const float*)d_in[21];
    const float* dW      = (const float*)d_in[22];
    const float* dB      = (const float*)d_in[23];
    float* out = (float*)d_out;

    float *p_h0, *p_agg1, *p_z, *p_h1, *p_agg2, *p_h2, *p_sums, *p_cnt;
    uint32_t *p_wh;
    int *p_deg, *p_off, *p_pos, *p_elist;
    cudaGetSymbolAddress((void**)&p_h0,   g_h0);
    cudaGetSymbolAddress((void**)&p_agg1, g_agg1);
    cudaGetSymbolAddress((void**)&p_z,    g_z);
    cudaGetSymbolAddress((void**)&p_h1,   g_h1);
    cudaGetSymbolAddress((void**)&p_agg2, g_agg2);
    cudaGetSymbolAddress((void**)&p_h2,   g_h2);
    cudaGetSymbolAddress((void**)&p_sums, g_sums);
    cudaGetSymbolAddress((void**)&p_cnt,  g_cnt);
    cudaGetSymbolAddress((void**)&p_wh,   g_wh);
    cudaGetSymbolAddress((void**)&p_deg,  g_deg);
    cudaGetSymbolAddress((void**)&p_off,  g_off);
    cudaGetSymbolAddress((void**)&p_pos,  g_pos);
    cudaGetSymbolAddress((void**)&p_elist, g_elist);

    const dim3 gemmGrid(EMB / BN, (Nn + BM - 1) / BM);

    // 0) weight prep (packed fp16 pairs)
    wprep_kernel<<<(196608 + 255) / 256, 256>>>(g1w1, p_wh + WO1, 196608, EMB);
    wprep_kernel<<<(294912 + 255) / 256, 256>>>(g1w2, p_wh + WO2, 294912, EMB);
    wprep_kernel<<<(294912 + 255) / 256, 256>>>(g2w1, p_wh + WO3, 294912, EMB);
    wprep_kernel<<<(294912 + 255) / 256, 256>>>(g2w2, p_wh + WO4, 294912, EMB);

    // 0b) CSR build (dst-indexed; shared by both GIN layers)
    zero_kernel<<<(Nn / 4 + 255) / 256, 256>>>((float4*)p_deg, Nn / 4);
    count_kernel<<<(Ee + 255) / 256, 256>>>(ei, p_deg);
    scan_kernel<<<1, 1024>>>(p_deg, p_off, p_pos, Nn);
    fill_kernel<<<(Ee + 255) / 256, 256>>>(ei, p_pos, p_elist);

    // 1) temporal conv stack -> h0 (N x 512)
    conv_kernel<<<Nn, 256>>>(x, conv0_w, bn0_g, bn0_b, bn0_m, bn0_v,
                             conv1_w, conv2_w, bn2_g, bn2_b, bn2_m, bn2_v, p_h0);

    // 2) GIN1 aggregation: agg1[n] = h0[n] + sum in-neighbors
    gather_kernel<FIN><<<Nn, FIN / 4>>>(p_off, p_elist, p_h0, p_agg1);

    // 3) z1 = relu(agg1@W1 + b1), h1 = relu(z1@W2 + b2)
    gemm_fp16_kernel<<<gemmGrid, 256>>>(p_agg1, p_wh + WO1, g1b1, p_z, Nn, FIN, EMB, 1);
    gemm_fp16_kernel<<<gemmGrid, 256>>>(p_z, p_wh + WO2, g1b2, p_h1, Nn, EMB, EMB, 1);

    // 4) GIN2 aggregation
    gather_kernel<EMB><<<Nn, EMB / 4>>>(p_off, p_elist, p_h1, p_agg2);

    // 5) z2 = relu(agg2@W3 + b3), h2 = relu(z2@W4 + b4)
    gemm_fp16_kernel<<<gemmGrid, 256>>>(p_agg2, p_wh + WO3, g2b1, p_z, Nn, EMB, EMB, 1);
    gemm_fp16_kernel<<<gemmGrid, 256>>>(p_z, p_wh + WO4, g2b2, p_h2, Nn, EMB, EMB, 1);

    // 6) graph mean pool + dense + log_softmax
    {
        int n4s = Gg * EMB / 4;
        zero_kernel<<<(n4s + 255) / 256, 256>>>((float4*)p_sums, n4s);
        zero_kernel<<<1, 256>>>((float4*)p_cnt, Gg / 4);
        pool_kernel<<<Nn, EMB / 4>>>(batch, p_h2, p_sums, p_cnt);
        head_kernel<<<Gg, EMB / 4>>>(p_sums, p_cnt, dW, dB, out);
    }
}

// round 11
// speedup vs baseline: 4.4960x; 1.3535x over previous
#include <cuda_runtime.h>
#include <cuda_bf16.h>
#include <cuda_fp16.h>
#include <math.h>
#include <stdint.h>

#define Nn 20000
#define Tt 256
#define Ee 320000
#define Gg 64
#define CT 8
#define CP 16
#define EMB 768
#define OUTC 4
#define FIN 512
#define BN_EPS 1e-5f

// ---------------- scratch (device globals, no allocation) ----------------
// fp16 activation buffers
__device__ __align__(16) __half g_h0h[(size_t)Nn * FIN];
__device__ __align__(16) __half g_agg1h[(size_t)Nn * FIN];
__device__ __align__(16) __half g_zh[(size_t)Nn * EMB];
__device__ __align__(16) __half g_h1h[(size_t)Nn * EMB];
__device__ __align__(16) __half g_agg2h[(size_t)Nn * EMB];
__device__ __align__(16) __half g_h2h[(size_t)Nn * EMB];
__device__ float g_sums[Gg * EMB];
__device__ float g_cnt[Gg];

// CSR scratch (built per launch; edges identical for both GIN layers)
__device__ int g_deg[Nn];
__device__ int g_off[Nn + 4];
__device__ int g_pos[Nn];
__device__ int g_elist[Ee];

// packed fp16x2 weight buffer: layout [K/2][M] uint32 (pair along k)
#define WO1 0
#define WO2 196608
#define WO3 491520
#define WO4 786432
#define WTOT 1081344
__device__ uint32_t g_wh[WTOT];

// ---------------- fused temporal conv + BN + pool (fp16 out) ----------------
__global__ void __launch_bounds__(256) conv_kernel(
    const float* __restrict__ x,
    const float* __restrict__ w0,
    const float* __restrict__ g0, const float* __restrict__ b0,
    const float* __restrict__ m0, const float* __restrict__ v0,
    const float* __restrict__ w1,
    const float* __restrict__ w2,
    const float* __restrict__ g2, const float* __restrict__ b2,
    const float* __restrict__ m2, const float* __restrict__ v2,
    __half* __restrict__ hout)
{
    __shared__ float xs[256];
    __shared__ float w0s[33 * 8];
    __shared__ float w1s[21 * 8];
    __shared__ float w2s[8 * 16];
    __shared__ float sc0[8], sh0[8], sc2[16], sh2[16];
    __shared__ float s1s[8][264];

    const int t = threadIdx.x;
    const int n = blockIdx.x;

    xs[t] = x[(size_t)n * Tt + t];
    for (int i = t; i < 33 * 8; i += 256) w0s[i] = w0[i];
    if (t < 21 * 8) w1s[t] = w1[t];
    if (t < 8 * 16) w2s[t] = w2[t];
    if (t < 8)  { float s = g0[t] * rsqrtf(v0[t] + BN_EPS); sc0[t] = s; sh0[t] = b0[t] - m0[t] * s; }
    if (t < 16) { float s = g2[t] * rsqrtf(v2[t] + BN_EPS); sc2[t] = s; sh2[t] = b2[t] - m2[t] * s; }
    __syncthreads();

    float acc[8];
#pragma unroll
    for (int c = 0; c < 8; c++) acc[c] = 0.f;
#pragma unroll
    for (int w = 0; w < 33; w++) {
        int tt = t + w - 16;
        float xv = (tt >= 0 && tt < 256) ? xs[tt] : 0.f;
#pragma unroll
        for (int c = 0; c < 8; c++) acc[c] += xv * w0s[w * 8 + c];
    }
#pragma unroll
    for (int c = 0; c < 8; c++) s1s[c][t] = acc[c] * sc0[c] + sh0[c];
    __syncthreads();

    float s2[8];
#pragma unroll
    for (int c = 0; c < 8; c++) {
        float a = 0.f;
#pragma unroll
        for (int w = 0; w < 21; w++) {
            int tt = t + w - 10;
            float xv = (tt >= 0 && tt < 256) ? s1s[c][tt] : 0.f;
            a += xv * w1s[w * 8 + c];
        }
        s2[c] = fmaxf(a, 0.f);
    }

    const int lane = t & 31;
#pragma unroll
    for (int o = 0; o < 16; o++) {
        float a = 0.f;
#pragma unroll
        for (int c = 0; c < 8; c++) a += s2[c] * w2s[c * 16 + o];
        a = fmaxf(a * sc2[o] + sh2[o], 0.f);
        a += __shfl_xor_sync(0xffffffffu, a, 1);
        a += __shfl_xor_sync(0xffffffffu, a, 2);
        a += __shfl_xor_sync(0xffffffffu, a, 4);
        if ((lane & 7) == 0)
            hout[(size_t)n * FIN + (t >> 3) * 16 + o] = __float2half(a * 0.125f);
    }
}

// ---------------- utility kernels ----------------
__global__ void zero_kernel(float4* __restrict__ p, int n4)
{
    int i = blockIdx.x * blockDim.x + threadIdx.x;
    int stride = gridDim.x * blockDim.x;
    float4 z = make_float4(0.f, 0.f, 0.f, 0.f);
    for (; i < n4; i += stride) p[i] = z;
}

// ---------------- weight prep: fp32 [K][M] -> packed fp16x2 [K/2][M] ----
__global__ void __launch_bounds__(256) wprep_kernel(
    const float* __restrict__ W, uint32_t* __restrict__ Wh, int total, int M)
{
    int idx = blockIdx.x * blockDim.x + threadIdx.x;
    if (idx >= total) return;
    int kp = idx / M, n = idx - kp * M;
    float f0 = W[(size_t)(2 * kp) * M + n];
    float f1 = W[(size_t)(2 * kp + 1) * M + n];
    __half2 h = __floats2half2_rn(f0, f1);
    Wh[idx] = *(uint32_t*)&h;
}

// ---------------- CSR build ----------------
__global__ void count_kernel(const int* __restrict__ ei, int* __restrict__ deg)
{
    int e = blockIdx.x * blockDim.x + threadIdx.x;
    if (e < Ee) atomicAdd(&deg[__ldg(ei + Ee + e)], 1);
}

__global__ void __launch_bounds__(1024) scan_kernel(
    const int* __restrict__ deg, int* __restrict__ off, int* __restrict__ pos, int n)
{
    __shared__ int wsum[32];
    __shared__ int sbase;
    const int tid = threadIdx.x, lane = tid & 31, wid = tid >> 5;
    if (tid == 0) sbase = 0;
    __syncthreads();
    for (int start = 0; start < n; start += 1024) {
        int idx = start + tid;
        int v = (idx < n) ? deg[idx] : 0;
        int x = v;
#pragma unroll
        for (int d = 1; d < 32; d <<= 1) {
            int y = __shfl_up_sync(0xffffffffu, x, d);
            if (lane >= d) x += y;
        }
        if (lane == 31) wsum[wid] = x;
        __syncthreads();
        if (wid == 0) {
            int w = wsum[lane];
#pragma unroll
            for (int d = 1; d < 32; d <<= 1) {
                int y = __shfl_up_sync(0xffffffffu, w, d);
                if (lane >= d) w += y;
            }
            wsum[lane] = w;
        }
        __syncthreads();
        int warpoff = (wid == 0) ? 0 : wsum[wid - 1];
        int excl = sbase + warpoff + x - v;
        if (idx < n) { off[idx] = excl; pos[idx] = excl; }
        int total = wsum[31];
        __syncthreads();
        if (tid == 0) sbase += total;
        __syncthreads();
    }
    if (tid == 0) off[n] = sbase;
}

__global__ void fill_kernel(const int* __restrict__ ei,
                            int* __restrict__ pos, int* __restrict__ elist)
{
    int e = blockIdx.x * blockDim.x + threadIdx.x;
    if (e < Ee) {
        int d = __ldg(ei + Ee + e);
        int p = atomicAdd(&pos[d], 1);
        elist[p] = __ldg(ei + e);
    }
}

// ---------------- CSR gather (fp16 in/out, fp32 accumulate) ------------------
// agg[n] = h[n] + sum_{src in in(n)} h[src]; one block per node, F/8 threads.
template <int F>
__global__ void __launch_bounds__(F / 8) gather_kernel(
    const int* __restrict__ off, const int* __restrict__ elist,
    const __half* __restrict__ h, __half* __restrict__ agg)
{
    const int n = blockIdx.x;
    const int f = threadIdx.x;  // F/8 threads, 8 halves each
    float a[8];
    {
        uint4 u = __ldg((const uint4*)(h + (size_t)n * F) + f);
        float2 p0 = __half22float2(*(__half2*)&u.x);
        float2 p1 = __half22float2(*(__half2*)&u.y);
        float2 p2 = __half22float2(*(__half2*)&u.z);
        float2 p3 = __half22float2(*(__half2*)&u.w);
        a[0] = p0.x; a[1] = p0.y; a[2] = p1.x; a[3] = p1.y;
        a[4] = p2.x; a[5] = p2.y; a[6] = p3.x; a[7] = p3.y;
    }
    int s = __ldg(off + n);
    const int e = __ldg(off + n + 1);
    for (; s + 1 < e; s += 2) {
        int s0 = __ldg(elist + s);
        int s1 = __ldg(elist + s + 1);
        uint4 u0 = __ldg((const uint4*)(h + (size_t)s0 * F) + f);
        uint4 u1 = __ldg((const uint4*)(h + (size_t)s1 * F) + f);
        float2 q;
        q = __half22float2(*(__half2*)&u0.x); a[0] += q.x; a[1] += q.y;
        q = __half22float2(*(__half2*)&u0.y); a[2] += q.x; a[3] += q.y;
        q = __half22float2(*(__half2*)&u0.z); a[4] += q.x; a[5] += q.y;
        q = __half22float2(*(__half2*)&u0.w); a[6] += q.x; a[7] += q.y;
        q = __half22float2(*(__half2*)&u1.x); a[0] += q.x; a[1] += q.y;
        q = __half22float2(*(__half2*)&u1.y); a[2] += q.x; a[3] += q.y;
        q = __half22float2(*(__half2*)&u1.z); a[4] += q.x; a[5] += q.y;
        q = __half22float2(*(__half2*)&u1.w); a[6] += q.x; a[7] += q.y;
    }
    if (s < e) {
        int s0 = __ldg(elist + s);
        uint4 u0 = __ldg((const uint4*)(h + (size_t)s0 * F) + f);
        float2 q;
        q = __half22float2(*(__half2*)&u0.x); a[0] += q.x; a[1] += q.y;
        q = __half22float2(*(__half2*)&u0.y); a[2] += q.x; a[3] += q.y;
        q = __half22float2(*(__half2*)&u0.z); a[4] += q.x; a[5] += q.y;
        q = __half22float2(*(__half2*)&u0.w); a[6] += q.x; a[7] += q.y;
    }
    uint4 o;
    __half2 h0 = __floats2half2_rn(a[0], a[1]);
    __half2 h1 = __floats2half2_rn(a[2], a[3]);
    __half2 h2 = __floats2half2_rn(a[4], a[5]);
    __half2 h3 = __floats2half2_rn(a[6], a[7]);
    o.x = *(uint32_t*)&h0; o.y = *(uint32_t*)&h1;
    o.z = *(uint32_t*)&h2; o.w = *(uint32_t*)&h3;
    *((uint4*)(agg + (size_t)n * F) + f) = o;
}

// ---------------- fp16 single-pass tensor-core GEMM ---------------------------
// C = act(A @ B + bias); A: Nrows x K fp16 row-major, B packed fp16 [K/2][M].
// Block tile 128x128, BK=32, 256 threads, warps 4(m) x 2(n), warp tile 32x64.
#define BM 128
#define BN 128
#define BK 32
#define KP 16          // uint32 (half2) per row per k-tile
#define AS_STRIDE 20   // KP + 4
#define BS_STRIDE 136  // BN + 8

__device__ __forceinline__ void mma_fp16(
    float* d, const uint32_t* a, uint32_t b0, uint32_t b1)
{
    asm volatile(
        "mma.sync.aligned.m16n8k16.row.col.f32.f16.f16.f32 "
        "{%0,%1,%2,%3}, {%4,%5,%6,%7}, {%8,%9}, {%0,%1,%2,%3};"
        : "+f"(d[0]), "+f"(d[1]), "+f"(d[2]), "+f"(d[3])
        : "r"(a[0]), "r"(a[1]), "r"(a[2]), "r"(a[3]), "r"(b0), "r"(b1));
}

__global__ void __launch_bounds__(256, 2) gemm_fp16_kernel(
    const __half* __restrict__ A,
    const uint32_t* __restrict__ Bh,
    const float* __restrict__ bias,
    __half* __restrict__ C, int Nrows, int K, int M, int doRelu)
{
    __shared__ uint32_t As[BM][AS_STRIDE];
    __shared__ uint32_t Bs[KP][BS_STRIDE];

    const int tid = threadIdx.x;
    const int lane = tid & 31;
    const int warp = tid >> 5;
    const int warp_m = warp & 3;
    const int warp_n = warp >> 2;
    const int rowBase = blockIdx.y * BM;
    const int colBase = blockIdx.x * BN;

    const int r0 = tid >> 2;      // 0..63 (rows r0, r0+64)
    const int c4 = tid & 3;       // uint4 index within row's k-tile
    const int kp0 = tid >> 5;     // 0..7 (kpairs kp0, kp0+8)
    const int n4 = tid & 31;      // 0..31

    float acc[2][8][4];
#pragma unroll
    for (int i = 0; i < 2; i++)
#pragma unroll
        for (int j = 0; j < 8; j++)
#pragma unroll
            for (int r = 0; r < 4; r++) acc[i][j][r] = 0.f;

    uint4 aReg[2], bReg[2];

    // ---- prefetch k0 = 0 ----
    {
#pragma unroll
        for (int h = 0; h < 2; h++) {
            int r = rowBase + r0 + h * 64;
            aReg[h] = (r < Nrows) ? ((const uint4*)(A + (size_t)r * K))[c4]
                                  : make_uint4(0, 0, 0, 0);
        }
#pragma unroll
        for (int h = 0; h < 2; h++) {
            size_t off = (size_t)(kp0 + h * 8) * M + colBase + n4 * 4;
            bReg[h] = *(const uint4*)(Bh + off);
        }
    }

    for (int k0 = 0; k0 < K; k0 += BK) {
        // ---- store staged regs to smem ----
#pragma unroll
        for (int h = 0; h < 2; h++) {
            *(uint4*)&As[r0 + h * 64][c4 * 4] = aReg[h];
        }
#pragma unroll
        for (int h = 0; h < 2; h++) {
            *(uint4*)&Bs[kp0 + h * 8][n4 * 4] = bReg[h];
        }
        __syncthreads();

        // ---- prefetch next ----
        if (k0 + BK < K) {
            const int kn = k0 + BK;
#pragma unroll
            for (int h = 0; h < 2; h++) {
                int r = rowBase + r0 + h * 64;
                aReg[h] = (r < Nrows) ? ((const uint4*)(A + (size_t)r * K + kn))[c4]
                                      : make_uint4(0, 0, 0, 0);
            }
#pragma unroll
            for (int h = 0; h < 2; h++) {
                size_t off = (size_t)(kn / 2 + kp0 + h * 8) * M + colBase + n4 * 4;
                bReg[h] = *(const uint4*)(Bh + off);
            }
        }

        // ---- compute: 2 k16 steps, 1 MMA pass ----
#pragma unroll
        for (int step = 0; step < 2; step++) {
            const int koff = step * 8;
            uint32_t a[2][4];
#pragma unroll
            for (int i = 0; i < 2; i++) {
                int mr = warp_m * 32 + i * 16 + (lane >> 2);
                int kc = koff + (lane & 3);
                a[i][0] = As[mr][kc];
                a[i][1] = As[mr + 8][kc];
                a[i][2] = As[mr][kc + 4];
                a[i][3] = As[mr + 8][kc + 4];
            }
#pragma unroll
            for (int j = 0; j < 8; j++) {
                int kb = koff + (lane & 3);
                int nb = warp_n * 64 + j * 8 + (lane >> 2);
                uint32_t b0 = Bs[kb][nb];
                uint32_t b1 = Bs[kb + 4][nb];
#pragma unroll
                for (int i = 0; i < 2; i++) {
                    mma_fp16(acc[i][j], a[i], b0, b1);
                }
            }
        }
        __syncthreads();
    }

    // ---- epilogue: bias + relu, pack half2 stores ----
#pragma unroll
    for (int i = 0; i < 2; i++) {
        int r = rowBase + warp_m * 32 + i * 16 + (lane >> 2);
#pragma unroll
        for (int j = 0; j < 8; j++) {
            int c0 = colBase + warp_n * 64 + j * 8 + (lane & 3) * 2;
            float b0v = bias[c0];
            float b1v = bias[c0 + 1];
            float v0 = acc[i][j][0] + b0v;
            float v1 = acc[i][j][1] + b1v;
            float v2 = acc[i][j][2] + b0v;
            float v3 = acc[i][j][3] + b1v;
            if (doRelu) {
                v0 = fmaxf(v0, 0.f); v1 = fmaxf(v1, 0.f);
                v2 = fmaxf(v2, 0.f); v3 = fmaxf(v3, 0.f);
            }
            if (r < Nrows) {
                __half2 p = __floats2half2_rn(v0, v1);
                *(uint32_t*)(C + (size_t)r * M + c0) = *(uint32_t*)&p;
            }
            if (r + 8 < Nrows) {
                __half2 p = __floats2half2_rn(v2, v3);
                *(uint32_t*)(C + (size_t)(r + 8) * M + c0) = *(uint32_t*)&p;
            }
        }
    }
}

// ---------------- graph mean-pool: sums/counts (fp16 in, red.v4) -------------
__global__ void __launch_bounds__(192) pool_kernel(
    const int* __restrict__ batch, const __half* __restrict__ h,
    float* __restrict__ sums, float* __restrict__ cnt)
{
    const int n = blockIdx.x;
    const int b = __ldg(batch + n);
    const int f = threadIdx.x;  // 192 threads, 4 halves each
    uint2 u = __ldg((const uint2*)(h + (size_t)n * EMB) + f);
    float2 p0 = __half22float2(*(__half2*)&u.x);
    float2 p1 = __half22float2(*(__half2*)&u.y);
    float* s = sums + (size_t)b * EMB + f * 4;
    asm volatile("red.global.add.v4.f32 [%0], {%1,%2,%3,%4};"
                 :: "l"(s), "f"(p0.x), "f"(p0.y), "f"(p1.x), "f"(p1.y) : "memory");
    if (f == 0) atomicAdd(&cnt[b], 1.0f);
}

// ---------------- head: mean, dense, log_softmax ----------------
__global__ void __launch_bounds__(192) head_kernel(
    const float* __restrict__ sums, const float* __restrict__ cnt,
    const float* __restrict__ W, const float* __restrict__ bias,
    float* __restrict__ out)
{
    __shared__ float red[192][4];
    const int g = blockIdx.x;
    const int t = threadIdx.x;
    const float c = fmaxf(cnt[g], 1.f);
    float4 p = *(const float4*)(sums + (size_t)g * EMB + t * 4);
    const float inv = 1.f / c;
    p.x *= inv; p.y *= inv; p.z *= inv; p.w *= inv;
    const int f = t * 4;
#pragma unroll
    for (int o = 0; o < 4; o++) {
        red[t][o] = p.x * W[(f + 0) * 4 + o] + p.y * W[(f + 1) * 4 + o] +
                    p.z * W[(f + 2) * 4 + o] + p.w * W[(f + 3) * 4 + o];
    }
    __syncthreads();
    if (t == 0) {
        float l[4];
#pragma unroll
        for (int o = 0; o < 4; o++) {
            float s = bias[o];
            for (int i = 0; i < 192; i++) s += red[i][o];
            l[o] = s;
        }
        float m = fmaxf(fmaxf(l[0], l[1]), fmaxf(l[2], l[3]));
        float se = expf(l[0] - m) + expf(l[1] - m) + expf(l[2] - m) + expf(l[3] - m);
        float lse = m + logf(se);
#pragma unroll
        for (int o = 0; o < 4; o++) out[g * 4 + o] = l[o] - lse;
    }
}

// ---------------- launch ----------------
extern "C" void kernel_launch(void* const* d_in, const int* in_sizes, int n_in,
                              void* d_out, int out_size)
{
    const float* x       = (const float*)d_in[0];
    const int*   ei      = (const int*)d_in[1];
    const int*   batch   = (const int*)d_in[2];
    const float* conv0_w = (const float*)d_in[3];
    const float* bn0_g   = (const float*)d_in[4];
    const float* bn0_b   = (const float*)d_in[5];
    const float* bn0_m   = (const float*)d_in[6];
    const float* bn0_v   = (const float*)d_in[7];
    const float* conv1_w = (const float*)d_in[8];
    const float* conv2_w = (const float*)d_in[9];
    const float* bn2_g   = (const float*)d_in[10];
    const float* bn2_b   = (const float*)d_in[11];
    const float* bn2_m   = (const float*)d_in[12];
    const float* bn2_v   = (const float*)d_in[13];
    const float* g1w1    = (const float*)d_in[14];
    const float* g1b1    = (const float*)d_in[15];
    const float* g1w2    = (const float*)d_in[16];
    const float* g1b2    = (const float*)d_in[17];
    const float* g2w1    = (const float*)d_in[18];
    const float* g2b1    = (const float*)d_in[19];
    const float* g2w2    = (const float*)d_in[20];
    const float* g2b2    = (const float*)d_in[21];
    const float* dW      = (const float*)d_in[22];
    const float* dB      = (const float*)d_in[23];
    float* out = (float*)d_out;

    __half *p_h0, *p_agg1, *p_z, *p_h1, *p_agg2, *p_h2;
    float *p_sums, *p_cnt;
    uint32_t *p_wh;
    int *p_deg, *p_off, *p_pos, *p_elist;
    cudaGetSymbolAddress((void**)&p_h0,   g_h0h);
    cudaGetSymbolAddress((void**)&p_agg1, g_agg1h);
    cudaGetSymbolAddress((void**)&p_z,    g_zh);
    cudaGetSymbolAddress((void**)&p_h1,   g_h1h);
    cudaGetSymbolAddress((void**)&p_agg2, g_agg2h);
    cudaGetSymbolAddress((void**)&p_h2,   g_h2h);
    cudaGetSymbolAddress((void**)&p_sums, g_sums);
    cudaGetSymbolAddress((void**)&p_cnt,  g_cnt);
    cudaGetSymbolAddress((void**)&p_wh,   g_wh);
    cudaGetSymbolAddress((void**)&p_deg,  g_deg);
    cudaGetSymbolAddress((void**)&p_off,  g_off);
    cudaGetSymbolAddress((void**)&p_pos,  g_pos);
    cudaGetSymbolAddress((void**)&p_elist, g_elist);

    const dim3 gemmGrid(EMB / BN, (Nn + BM - 1) / BM);

    // 0) weight prep (packed fp16 pairs)
    wprep_kernel<<<(196608 + 255) / 256, 256>>>(g1w1, p_wh + WO1, 196608, EMB);
    wprep_kernel<<<(294912 + 255) / 256, 256>>>(g1w2, p_wh + WO2, 294912, EMB);
    wprep_kernel<<<(294912 + 255) / 256, 256>>>(g2w1, p_wh + WO3, 294912, EMB);
    wprep_kernel<<<(294912 + 255) / 256, 256>>>(g2w2, p_wh + WO4, 294912, EMB);

    // 0b) CSR build (dst-indexed; shared by both GIN layers)
    zero_kernel<<<(Nn / 4 + 255) / 256, 256>>>((float4*)p_deg, Nn / 4);
    count_kernel<<<(Ee + 255) / 256, 256>>>(ei, p_deg);
    scan_kernel<<<1, 1024>>>(p_deg, p_off, p_pos, Nn);
    fill_kernel<<<(Ee + 255) / 256, 256>>>(ei, p_pos, p_elist);

    // 1) temporal conv stack -> h0 (N x 512, fp16)
    conv_kernel<<<Nn, 256>>>(x, conv0_w, bn0_g, bn0_b, bn0_m, bn0_v,
                             conv1_w, conv2_w, bn2_g, bn2_b, bn2_m, bn2_v, p_h0);

    // 2) GIN1 aggregation: agg1[n] = h0[n] + sum in-neighbors
    gather_kernel<FIN><<<Nn, FIN / 8>>>(p_off, p_elist, p_h0, p_agg1);

    // 3) z1 = relu(agg1@W1 + b1), h1 = relu(z1@W2 + b2)
    gemm_fp16_kernel<<<gemmGrid, 256>>>(p_agg1, p_wh + WO1, g1b1, p_z, Nn, FIN, EMB, 1);
    gemm_fp16_kernel<<<gemmGrid, 256>>>(p_z, p_wh + WO2, g1b2, p_h1, Nn, EMB, EMB, 1);

    // 4) GIN2 aggregation
    gather_kernel<EMB><<<Nn, EMB / 8>>>(p_off, p_elist, p_h1, p_agg2);

    // 5) z2 = relu(agg2@W3 + b3), h2 = relu(z2@W4 + b4)
    gemm_fp16_kernel<<<gemmGrid, 256>>>(p_agg2, p_wh + WO3, g2b1, p_z, Nn, EMB, EMB, 1);
    gemm_fp16_kernel<<<gemmGrid, 256>>>(p_z, p_wh + WO4, g2b2, p_h2, Nn, EMB, EMB, 1);

    // 6) graph mean pool + dense + log_softmax
    {
        int n4s = Gg * EMB / 4;
        zero_kernel<<<(n4s + 255) / 256, 256>>>((float4*)p_sums, n4s);
        zero_kernel<<<1, 256>>>((float4*)p_cnt, Gg / 4);
        pool_kernel<<<Nn, EMB / 4>>>(batch, p_h2, p_sums, p_cnt);
        head_kernel<<<Gg, EMB / 4>>>(p_sums, p_cnt, dW, dB, out);
    }
}

// round 12
// speedup vs baseline: 4.6499x; 1.0342x over previous
#include <cuda_runtime.h>
#include <cuda_bf16.h>
#include <cuda_fp16.h>
#include <math.h>
#include <stdint.h>

#define Nn 20000
#define Tt 256
#define Ee 320000
#define Gg 64
#define CT 8
#define CP 16
#define EMB 768
#define OUTC 4
#define FIN 512
#define BN_EPS 1e-5f

// ---------------- scratch (device globals, no allocation) ----------------
__device__ __align__(16) __half g_h0h[(size_t)Nn * FIN];
__device__ __align__(16) __half g_agg1h[(size_t)Nn * FIN];
__device__ __align__(16) __half g_zh[(size_t)Nn * EMB];
__device__ __align__(16) __half g_h1h[(size_t)Nn * EMB];
__device__ __align__(16) __half g_agg2h[(size_t)Nn * EMB];
__device__ __align__(16) __half g_h2h[(size_t)Nn * EMB];
__device__ float g_sums[Gg * EMB];
__device__ float g_cnt[Gg];

// CSR scratch
__device__ int g_deg[Nn];
__device__ int g_off[Nn + 4];
__device__ int g_pos[Nn];
__device__ int g_elist[Ee];

// packed fp16x2 weight buffer: layout [K/2][M] uint32 (pair along k)
#define WO1 0
#define WO2 196608
#define WO3 491520
#define WO4 786432
#define WTOT 1081344
__device__ uint32_t g_wh[WTOT];

// ---------------- fused temporal conv + BN + pool (fp16 out) ----------------
__global__ void __launch_bounds__(256) conv_kernel(
    const float* __restrict__ x,
    const float* __restrict__ w0,
    const float* __restrict__ g0, const float* __restrict__ b0,
    const float* __restrict__ m0, const float* __restrict__ v0,
    const float* __restrict__ w1,
    const float* __restrict__ w2,
    const float* __restrict__ g2, const float* __restrict__ b2,
    const float* __restrict__ m2, const float* __restrict__ v2,
    __half* __restrict__ hout)
{
    __shared__ float xs[256];
    __shared__ float w0s[33 * 8];
    __shared__ float w1s[21 * 8];
    __shared__ float w2s[8 * 16];
    __shared__ float sc0[8], sh0[8], sc2[16], sh2[16];
    __shared__ float s1s[8][264];

    const int t = threadIdx.x;
    const int n = blockIdx.x;

    xs[t] = x[(size_t)n * Tt + t];
    for (int i = t; i < 33 * 8; i += 256) w0s[i] = w0[i];
    if (t < 21 * 8) w1s[t] = w1[t];
    if (t < 8 * 16) w2s[t] = w2[t];
    if (t < 8)  { float s = g0[t] * rsqrtf(v0[t] + BN_EPS); sc0[t] = s; sh0[t] = b0[t] - m0[t] * s; }
    if (t < 16) { float s = g2[t] * rsqrtf(v2[t] + BN_EPS); sc2[t] = s; sh2[t] = b2[t] - m2[t] * s; }
    __syncthreads();

    float acc[8];
#pragma unroll
    for (int c = 0; c < 8; c++) acc[c] = 0.f;
#pragma unroll
    for (int w = 0; w < 33; w++) {
        int tt = t + w - 16;
        float xv = (tt >= 0 && tt < 256) ? xs[tt] : 0.f;
#pragma unroll
        for (int c = 0; c < 8; c++) acc[c] += xv * w0s[w * 8 + c];
    }
#pragma unroll
    for (int c = 0; c < 8; c++) s1s[c][t] = acc[c] * sc0[c] + sh0[c];
    __syncthreads();

    float s2[8];
#pragma unroll
    for (int c = 0; c < 8; c++) {
        float a = 0.f;
#pragma unroll
        for (int w = 0; w < 21; w++) {
            int tt = t + w - 10;
            float xv = (tt >= 0 && tt < 256) ? s1s[c][tt] : 0.f;
            a += xv * w1s[w * 8 + c];
        }
        s2[c] = fmaxf(a, 0.f);
    }

    const int lane = t & 31;
#pragma unroll
    for (int o = 0; o < 16; o++) {
        float a = 0.f;
#pragma unroll
        for (int c = 0; c < 8; c++) a += s2[c] * w2s[c * 16 + o];
        a = fmaxf(a * sc2[o] + sh2[o], 0.f);
        a += __shfl_xor_sync(0xffffffffu, a, 1);
        a += __shfl_xor_sync(0xffffffffu, a, 2);
        a += __shfl_xor_sync(0xffffffffu, a, 4);
        if ((lane & 7) == 0)
            hout[(size_t)n * FIN + (t >> 3) * 16 + o] = __float2half(a * 0.125f);
    }
}

// ---------------- utility kernels ----------------
__global__ void zero_kernel(float4* __restrict__ p, int n4)
{
    int i = blockIdx.x * blockDim.x + threadIdx.x;
    int stride = gridDim.x * blockDim.x;
    float4 z = make_float4(0.f, 0.f, 0.f, 0.f);
    for (; i < n4; i += stride) p[i] = z;
}

// ---------------- weight prep: all 4 fp32 [K][M] -> packed fp16x2 [K/2][M] ----
__global__ void __launch_bounds__(256) wprep_all_kernel(
    const float* __restrict__ w1, const float* __restrict__ w2,
    const float* __restrict__ w3, const float* __restrict__ w4,
    uint32_t* __restrict__ Wh)
{
    int idx = blockIdx.x * blockDim.x + threadIdx.x;
    if (idx >= WTOT) return;
    const float* W;
    int local;
    if (idx < WO2)      { W = w1; local = idx; }
    else if (idx < WO3) { W = w2; local = idx - WO2; }
    else if (idx < WO4) { W = w3; local = idx - WO3; }
    else                { W = w4; local = idx - WO4; }
    int kp = local / EMB, n = local - kp * EMB;
    float f0 = W[(size_t)(2 * kp) * EMB + n];
    float f1 = W[(size_t)(2 * kp + 1) * EMB + n];
    __half2 h = __floats2half2_rn(f0, f1);
    Wh[idx] = *(uint32_t*)&h;
}

// ---------------- CSR build ----------------
__global__ void count_kernel(const int* __restrict__ ei, int* __restrict__ deg)
{
    int e = blockIdx.x * blockDim.x + threadIdx.x;
    if (e < Ee) atomicAdd(&deg[__ldg(ei + Ee + e)], 1);
}

__global__ void __launch_bounds__(1024) scan_kernel(
    const int* __restrict__ deg, int* __restrict__ off, int* __restrict__ pos, int n)
{
    __shared__ int wsum[32];
    __shared__ int sbase;
    const int tid = threadIdx.x, lane = tid & 31, wid = tid >> 5;
    if (tid == 0) sbase = 0;
    __syncthreads();
    for (int start = 0; start < n; start += 1024) {
        int idx = start + tid;
        int v = (idx < n) ? deg[idx] : 0;
        int x = v;
#pragma unroll
        for (int d = 1; d < 32; d <<= 1) {
            int y = __shfl_up_sync(0xffffffffu, x, d);
            if (lane >= d) x += y;
        }
        if (lane == 31) wsum[wid] = x;
        __syncthreads();
        if (wid == 0) {
            int w = wsum[lane];
#pragma unroll
            for (int d = 1; d < 32; d <<= 1) {
                int y = __shfl_up_sync(0xffffffffu, w, d);
                if (lane >= d) w += y;
            }
            wsum[lane] = w;
        }
        __syncthreads();
        int warpoff = (wid == 0) ? 0 : wsum[wid - 1];
        int excl = sbase + warpoff + x - v;
        if (idx < n) { off[idx] = excl; pos[idx] = excl; }
        int total = wsum[31];
        __syncthreads();
        if (tid == 0) sbase += total;
        __syncthreads();
    }
    if (tid == 0) off[n] = sbase;
}

__global__ void fill_kernel(const int* __restrict__ ei,
                            int* __restrict__ pos, int* __restrict__ elist)
{
    int e = blockIdx.x * blockDim.x + threadIdx.x;
    if (e < Ee) {
        int d = __ldg(ei + Ee + e);
        int p = atomicAdd(&pos[d], 1);
        elist[p] = __ldg(ei + e);
    }
}

// ---------------- CSR gather (fp16 in/out, fp32 accumulate, 4-way MLP) --------
template <int F>
__global__ void __launch_bounds__(F / 8) gather_kernel(
    const int* __restrict__ off, const int* __restrict__ elist,
    const __half* __restrict__ h, __half* __restrict__ agg)
{
    const int n = blockIdx.x;
    const int f = threadIdx.x;  // F/8 threads, 8 halves each
    float a[8];
    {
        uint4 u = __ldg((const uint4*)(h + (size_t)n * F) + f);
        float2 p0 = __half22float2(*(__half2*)&u.x);
        float2 p1 = __half22float2(*(__half2*)&u.y);
        float2 p2 = __half22float2(*(__half2*)&u.z);
        float2 p3 = __half22float2(*(__half2*)&u.w);
        a[0] = p0.x; a[1] = p0.y; a[2] = p1.x; a[3] = p1.y;
        a[4] = p2.x; a[5] = p2.y; a[6] = p3.x; a[7] = p3.y;
    }
    int s = __ldg(off + n);
    const int e = __ldg(off + n + 1);
#define ACCUM(u) do { \
        float2 q; \
        q = __half22float2(*(__half2*)&(u).x); a[0] += q.x; a[1] += q.y; \
        q = __half22float2(*(__half2*)&(u).y); a[2] += q.x; a[3] += q.y; \
        q = __half22float2(*(__half2*)&(u).z); a[4] += q.x; a[5] += q.y; \
        q = __half22float2(*(__half2*)&(u).w); a[6] += q.x; a[7] += q.y; \
    } while (0)
    for (; s + 3 < e; s += 4) {
        int s0 = __ldg(elist + s);
        int s1 = __ldg(elist + s + 1);
        int s2 = __ldg(elist + s + 2);
        int s3 = __ldg(elist + s + 3);
        uint4 u0 = __ldg((const uint4*)(h + (size_t)s0 * F) + f);
        uint4 u1 = __ldg((const uint4*)(h + (size_t)s1 * F) + f);
        uint4 u2 = __ldg((const uint4*)(h + (size_t)s2 * F) + f);
        uint4 u3 = __ldg((const uint4*)(h + (size_t)s3 * F) + f);
        ACCUM(u0); ACCUM(u1); ACCUM(u2); ACCUM(u3);
    }
    for (; s < e; s++) {
        int s0 = __ldg(elist + s);
        uint4 u0 = __ldg((const uint4*)(h + (size_t)s0 * F) + f);
        ACCUM(u0);
    }
#undef ACCUM
    uint4 o;
    __half2 h0 = __floats2half2_rn(a[0], a[1]);
    __half2 h1 = __floats2half2_rn(a[2], a[3]);
    __half2 h2 = __floats2half2_rn(a[4], a[5]);
    __half2 h3 = __floats2half2_rn(a[6], a[7]);
    o.x = *(uint32_t*)&h0; o.y = *(uint32_t*)&h1;
    o.z = *(uint32_t*)&h2; o.w = *(uint32_t*)&h3;
    *((uint4*)(agg + (size_t)n * F) + f) = o;
}

// ---------------- fp16 GEMM with 3-stage cp.async pipeline --------------------
// C = act(A @ B + bias); A: Nrows x K fp16, B packed fp16 [K/2][M].
// 128x128 tile, BK=32, 256 threads, warps 4(m)x2(n), one __syncthreads per tile.
#define BM 128
#define BN 128
#define BK 32
#define KP 16
#define AS_STRIDE 20
#define BS_STRIDE 136
#define NSTAGE 3
#define AS_ELEMS (BM * AS_STRIDE)
#define BS_ELEMS (KP * BS_STRIDE)
#define GEMM_SMEM_BYTES ((NSTAGE * (AS_ELEMS + BS_ELEMS)) * 4)

__device__ __forceinline__ void cp_async16(uint32_t dst, const void* src, int sz)
{
    asm volatile("cp.async.cg.shared.global [%0], [%1], 16, %2;"
                 :: "r"(dst), "l"(src), "r"(sz));
}
__device__ __forceinline__ void cp_commit()
{
    asm volatile("cp.async.commit_group;");
}

__device__ __forceinline__ void mma_fp16(
    float* d, const uint32_t* a, uint32_t b0, uint32_t b1)
{
    asm volatile(
        "mma.sync.aligned.m16n8k16.row.col.f32.f16.f16.f32 "
        "{%0,%1,%2,%3}, {%4,%5,%6,%7}, {%8,%9}, {%0,%1,%2,%3};"
        : "+f"(d[0]), "+f"(d[1]), "+f"(d[2]), "+f"(d[3])
        : "r"(a[0]), "r"(a[1]), "r"(a[2]), "r"(a[3]), "r"(b0), "r"(b1));
}

__global__ void __launch_bounds__(256, 2) gemm_fp16_kernel(
    const __half* __restrict__ A,
    const uint32_t* __restrict__ Bh,
    const float* __restrict__ bias,
    __half* __restrict__ C, int Nrows, int K, int M, int doRelu)
{
    extern __shared__ uint32_t smem[];
    uint32_t* AsBase = smem;                       // [NSTAGE][BM][AS_STRIDE]
    uint32_t* BsBase = smem + NSTAGE * AS_ELEMS;   // [NSTAGE][KP][BS_STRIDE]

    const int tid = threadIdx.x;
    const int lane = tid & 31;
    const int warp = tid >> 5;
    const int warp_m = warp & 3;
    const int warp_n = warp >> 2;
    const int rowBase = blockIdx.y * BM;
    const int colBase = blockIdx.x * BN;

    const int r0 = tid >> 2;      // 0..63 (rows r0, r0+64)
    const int c4 = tid & 3;       // uint4 chunk within k-tile
    const int kp0 = tid >> 5;     // 0..7 (kpairs kp0, kp0+8)
    const int n4 = tid & 31;      // 0..31

    // global srcs (clamped rows; zero-fill via src-size 0)
    int rowA0 = rowBase + r0, rowA1 = rowBase + r0 + 64;
    const int sz0 = (rowA0 < Nrows) ? 16 : 0;
    const int sz1 = (rowA1 < Nrows) ? 16 : 0;
    if (rowA0 >= Nrows) rowA0 = Nrows - 1;
    if (rowA1 >= Nrows) rowA1 = Nrows - 1;
    const __half* aSrc0 = A + (size_t)rowA0 * K + c4 * 8;
    const __half* aSrc1 = A + (size_t)rowA1 * K + c4 * 8;
    const uint32_t* bSrc0 = Bh + (size_t)kp0 * M + colBase + n4 * 4;
    const uint32_t* bSrc1 = Bh + (size_t)(kp0 + 8) * M + colBase + n4 * 4;

    // smem dst addresses per stage
    uint32_t adst0[NSTAGE], adst1[NSTAGE], bdst0[NSTAGE], bdst1[NSTAGE];
#pragma unroll
    for (int b = 0; b < NSTAGE; b++) {
        adst0[b] = (uint32_t)__cvta_generic_to_shared(
            &AsBase[b * AS_ELEMS + r0 * AS_STRIDE + c4 * 4]);
        adst1[b] = (uint32_t)__cvta_generic_to_shared(
            &AsBase[b * AS_ELEMS + (r0 + 64) * AS_STRIDE + c4 * 4]);
        bdst0[b] = (uint32_t)__cvta_generic_to_shared(
            &BsBase[b * BS_ELEMS + kp0 * BS_STRIDE + n4 * 4]);
        bdst1[b] = (uint32_t)__cvta_generic_to_shared(
            &BsBase[b * BS_ELEMS + (kp0 + 8) * BS_STRIDE + n4 * 4]);
    }

    float acc[2][8][4];
#pragma unroll
    for (int i = 0; i < 2; i++)
#pragma unroll
        for (int j = 0; j < 8; j++)
#pragma unroll
            for (int r = 0; r < 4; r++) acc[i][j][r] = 0.f;

    const int nsteps = K / BK;

#define ISSUE(s) do { \
        int _b = (s) % NSTAGE; \
        cp_async16(adst0[_b], aSrc0 + (size_t)(s) * BK, sz0); \
        cp_async16(adst1[_b], aSrc1 + (size_t)(s) * BK, sz1); \
        cp_async16(bdst0[_b], bSrc0 + (size_t)(s) * KP * M, 16); \
        cp_async16(bdst1[_b], bSrc1 + (size_t)(s) * KP * M, 16); \
        cp_commit(); \
    } while (0)

    ISSUE(0);
    if (nsteps > 1) ISSUE(1);

    for (int s = 0; s < nsteps; s++) {
        if (s + 1 < nsteps) asm volatile("cp.async.wait_group 1;");
        else                asm volatile("cp.async.wait_group 0;");
        __syncthreads();
        if (s + 2 < nsteps) ISSUE(s + 2);

        const uint32_t* As = AsBase + (s % NSTAGE) * AS_ELEMS;
        const uint32_t* Bs = BsBase + (s % NSTAGE) * BS_ELEMS;

#pragma unroll
        for (int step = 0; step < 2; step++) {
            const int koff = step * 8;
            uint32_t a[2][4];
#pragma unroll
            for (int i = 0; i < 2; i++) {
                int mr = warp_m * 32 + i * 16 + (lane >> 2);
                int kc = koff + (lane & 3);
                a[i][0] = As[mr * AS_STRIDE + kc];
                a[i][1] = As[(mr + 8) * AS_STRIDE + kc];
                a[i][2] = As[mr * AS_STRIDE + kc + 4];
                a[i][3] = As[(mr + 8) * AS_STRIDE + kc + 4];
            }
#pragma unroll
            for (int j = 0; j < 8; j++) {
                int kb = koff + (lane & 3);
                int nb = warp_n * 64 + j * 8 + (lane >> 2);
                uint32_t b0 = Bs[kb * BS_STRIDE + nb];
                uint32_t b1 = Bs[(kb + 4) * BS_STRIDE + nb];
#pragma unroll
                for (int i = 0; i < 2; i++) {
                    mma_fp16(acc[i][j], a[i], b0, b1);
                }
            }
        }
        // no trailing sync: next iteration's wait+syncthreads orders buffer reuse
        // (stage s+2 writes buf (s+2)%3, untouched by compute of s and s+1)
    }
#undef ISSUE

    // ---- epilogue: bias + relu, pack half2 stores ----
#pragma unroll
    for (int i = 0; i < 2; i++) {
        int r = rowBase + warp_m * 32 + i * 16 + (lane >> 2);
#pragma unroll
        for (int j = 0; j < 8; j++) {
            int c0 = colBase + warp_n * 64 + j * 8 + (lane & 3) * 2;
            float b0v = bias[c0];
            float b1v = bias[c0 + 1];
            float v0 = acc[i][j][0] + b0v;
            float v1 = acc[i][j][1] + b1v;
            float v2 = acc[i][j][2] + b0v;
            float v3 = acc[i][j][3] + b1v;
            if (doRelu) {
                v0 = fmaxf(v0, 0.f); v1 = fmaxf(v1, 0.f);
                v2 = fmaxf(v2, 0.f); v3 = fmaxf(v3, 0.f);
            }
            if (r < Nrows) {
                __half2 p = __floats2half2_rn(v0, v1);
                *(uint32_t*)(C + (size_t)r * M + c0) = *(uint32_t*)&p;
            }
            if (r + 8 < Nrows) {
                __half2 p = __floats2half2_rn(v2, v3);
                *(uint32_t*)(C + (size_t)(r + 8) * M + c0) = *(uint32_t*)&p;
            }
        }
    }
}

// ---------------- graph mean-pool: sums/counts (fp16 in, red.v4) -------------
__global__ void __launch_bounds__(192) pool_kernel(
    const int* __restrict__ batch, const __half* __restrict__ h,
    float* __restrict__ sums, float* __restrict__ cnt)
{
    const int n = blockIdx.x;
    const int b = __ldg(batch + n);
    const int f = threadIdx.x;
    uint2 u = __ldg((const uint2*)(h + (size_t)n * EMB) + f);
    float2 p0 = __half22float2(*(__half2*)&u.x);
    float2 p1 = __half22float2(*(__half2*)&u.y);
    float* s = sums + (size_t)b * EMB + f * 4;
    asm volatile("red.global.add.v4.f32 [%0], {%1,%2,%3,%4};"
                 :: "l"(s), "f"(p0.x), "f"(p0.y), "f"(p1.x), "f"(p1.y) : "memory");
    if (f == 0) atomicAdd(&cnt[b], 1.0f);
}

// ---------------- head: mean, dense, log_softmax ----------------
__global__ void __launch_bounds__(192) head_kernel(
    const float* __restrict__ sums, const float* __restrict__ cnt,
    const float* __restrict__ W, const float* __restrict__ bias,
    float* __restrict__ out)
{
    __shared__ float red[192][4];
    const int g = blockIdx.x;
    const int t = threadIdx.x;
    const float c = fmaxf(cnt[g], 1.f);
    float4 p = *(const float4*)(sums + (size_t)g * EMB + t * 4);
    const float inv = 1.f / c;
    p.x *= inv; p.y *= inv; p.z *= inv; p.w *= inv;
    const int f = t * 4;
#pragma unroll
    for (int o = 0; o < 4; o++) {
        red[t][o] = p.x * W[(f + 0) * 4 + o] + p.y * W[(f + 1) * 4 + o] +
                    p.z * W[(f + 2) * 4 + o] + p.w * W[(f + 3) * 4 + o];
    }
    __syncthreads();
    if (t == 0) {
        float l[4];
#pragma unroll
        for (int o = 0; o < 4; o++) {
            float s = bias[o];
            for (int i = 0; i < 192; i++) s += red[i][o];
            l[o] = s;
        }
        float m = fmaxf(fmaxf(l[0], l[1]), fmaxf(l[2], l[3]));
        float se = expf(l[0] - m) + expf(l[1] - m) + expf(l[2] - m) + expf(l[3] - m);
        float lse = m + logf(se);
#pragma unroll
        for (int o = 0; o < 4; o++) out[g * 4 + o] = l[o] - lse;
    }
}

// ---------------- launch ----------------
extern "C" void kernel_launch(void* const* d_in, const int* in_sizes, int n_in,
                              void* d_out, int out_size)
{
    const float* x       = (const float*)d_in[0];
    const int*   ei      = (const int*)d_in[1];
    const int*   batch   = (const int*)d_in[2];
    const float* conv0_w = (const float*)d_in[3];
    const float* bn0_g   = (const float*)d_in[4];
    const float* bn0_b   = (const float*)d_in[5];
    const float* bn0_m   = (const float*)d_in[6];
    const float* bn0_v   = (const float*)d_in[7];
    const float* conv1_w = (const float*)d_in[8];
    const float* conv2_w = (const float*)d_in[9];
    const float* bn2_g   = (const float*)d_in[10];
    const float* bn2_b   = (const float*)d_in[11];
    const float* bn2_m   = (const float*)d_in[12];
    const float* bn2_v   = (const float*)d_in[13];
    const float* g1w1    = (const float*)d_in[14];
    const float* g1b1    = (const float*)d_in[15];
    const float* g1w2    = (const float*)d_in[16];
    const float* g1b2    = (const float*)d_in[17];
    const float* g2w1    = (const float*)d_in[18];
    const float* g2b1    = (const float*)d_in[19];
    const float* g2w2    = (const float*)d_in[20];
    const float* g2b2    = (const float*)d_in[21];
    const float* dW      = (const float*)d_in[22];
    const float* dB      = (const float*)d_in[23];
    float* out = (float*)d_out;

    __half *p_h0, *p_agg1, *p_z, *p_h1, *p_agg2, *p_h2;
    float *p_sums, *p_cnt;
    uint32_t *p_wh;
    int *p_deg, *p_off, *p_pos, *p_elist;
    cudaGetSymbolAddress((void**)&p_h0,   g_h0h);
    cudaGetSymbolAddress((void**)&p_agg1, g_agg1h);
    cudaGetSymbolAddress((void**)&p_z,    g_zh);
    cudaGetSymbolAddress((void**)&p_h1,   g_h1h);
    cudaGetSymbolAddress((void**)&p_agg2, g_agg2h);
    cudaGetSymbolAddress((void**)&p_h2,   g_h2h);
    cudaGetSymbolAddress((void**)&p_sums, g_sums);
    cudaGetSymbolAddress((void**)&p_cnt,  g_cnt);
    cudaGetSymbolAddress((void**)&p_wh,   g_wh);
    cudaGetSymbolAddress((void**)&p_deg,  g_deg);
    cudaGetSymbolAddress((void**)&p_off,  g_off);
    cudaGetSymbolAddress((void**)&p_pos,  g_pos);
    cudaGetSymbolAddress((void**)&p_elist, g_elist);

    cudaFuncSetAttribute(gemm_fp16_kernel,
                         cudaFuncAttributeMaxDynamicSharedMemorySize,
                         GEMM_SMEM_BYTES);

    const dim3 gemmGrid(EMB / BN, (Nn + BM - 1) / BM);

    // 0) weight prep (all four packed fp16 weights in one launch)
    wprep_all_kernel<<<(WTOT + 255) / 256, 256>>>(g1w1, g1w2, g2w1, g2w2, p_wh);

    // 0b) CSR build (dst-indexed; shared by both GIN layers)
    zero_kernel<<<(Nn / 4 + 255) / 256, 256>>>((float4*)p_deg, Nn / 4);
    count_kernel<<<(Ee + 255) / 256, 256>>>(ei, p_deg);
    scan_kernel<<<1, 1024>>>(p_deg, p_off, p_pos, Nn);
    fill_kernel<<<(Ee + 255) / 256, 256>>>(ei, p_pos, p_elist);

    // 1) temporal conv stack -> h0 (N x 512, fp16)
    conv_kernel<<<Nn, 256>>>(x, conv0_w, bn0_g, bn0_b, bn0_m, bn0_v,
                             conv1_w, conv2_w, bn2_g, bn2_b, bn2_m, bn2_v, p_h0);

    // 2) GIN1 aggregation
    gather_kernel<FIN><<<Nn, FIN / 8>>>(p_off, p_elist, p_h0, p_agg1);

    // 3) z1 = relu(agg1@W1 + b1), h1 = relu(z1@W2 + b2)
    gemm_fp16_kernel<<<gemmGrid, 256, GEMM_SMEM_BYTES>>>(p_agg1, p_wh + WO1, g1b1, p_z, Nn, FIN, EMB, 1);
    gemm_fp16_kernel<<<gemmGrid, 256, GEMM_SMEM_BYTES>>>(p_z, p_wh + WO2, g1b2, p_h1, Nn, EMB, EMB, 1);

    // 4) GIN2 aggregation
    gather_kernel<EMB><<<Nn, EMB / 8>>>(p_off, p_elist, p_h1, p_agg2);

    // 5) z2 = relu(agg2@W3 + b3), h2 = relu(z2@W4 + b4)
    gemm_fp16_kernel<<<gemmGrid, 256, GEMM_SMEM_BYTES>>>(p_agg2, p_wh + WO3, g2b1, p_z, Nn, EMB, EMB, 1);
    gemm_fp16_kernel<<<gemmGrid, 256, GEMM_SMEM_BYTES>>>(p_z, p_wh + WO4, g2b2, p_h2, Nn, EMB, EMB, 1);

    // 6) graph mean pool + dense + log_softmax
    {
        int n4s = Gg * EMB / 4;
        zero_kernel<<<(n4s + 255) / 256, 256>>>((float4*)p_sums, n4s);
        zero_kernel<<<1, 256>>>((float4*)p_cnt, Gg / 4);
        pool_kernel<<<Nn, EMB / 4>>>(batch, p_h2, p_sums, p_cnt);
        head_kernel<<<Gg, EMB / 4>>>(p_sums, p_cnt, dW, dB, out);
    }
}